// round 8
// baseline (speedup 1.0000x reference)
#include <cuda_runtime.h>
#include <cuda_fp16.h>
#include <math.h>
#include <stdint.h>

// ---------------- problem constants ----------------
#define L_SEQ 2048
#define DM    1024
#define DI    2048
#define NST   16
#define KC    4
#define NPROJ (DI + 2*NST)   // 2080

#define NCH   16
#define CH    128
#define TT    16
#define SD    64

// ---------------- scratch (device globals) ----------------
__device__ float g_xr  [L_SEQ * 2 * DI];
__device__ float g_xi  [L_SEQ * DI];
__device__ float g_proj[L_SEQ * NPROJ];

__device__ __half g_ahi[L_SEQ * DI];
__device__ __half g_alo[L_SEQ * DI];
__device__ __half g_win_h [2 * DI * DM];
__device__ __half g_wx_h  [NPROJ * DI];
__device__ __half g_wout_h[DM * DI];

__device__ float g_cA[NCH * DI * NST];
__device__ float g_cB[NCH * DI * NST];
__device__ float g_h0[NCH * DI * NST];

__device__ __forceinline__ float softplus_f(float x) {
    return fmaxf(x, 0.f) + log1pf(expf(-fabsf(x)));
}

// ---------------- PTX helpers ----------------
__device__ __forceinline__ uint32_t smem_u32(const void* p) {
    uint32_t a;
    asm("{ .reg .u64 t; cvta.to.shared.u64 t, %1; cvt.u32.u64 %0, t; }" : "=r"(a) : "l"(p));
    return a;
}
__device__ __forceinline__ void cp_async16(uint32_t sm, const void* gm) {
    asm volatile("cp.async.ca.shared.global [%0], [%1], 16;" :: "r"(sm), "l"(gm));
}
__device__ __forceinline__ void cp_async16p(void* sm, const void* gm) {
    cp_async16(smem_u32(sm), gm);
}
__device__ __forceinline__ void cp_commit() { asm volatile("cp.async.commit_group;"); }
template<int N> __device__ __forceinline__ void cp_wait() {
    asm volatile("cp.async.wait_group %0;" :: "n"(N));
}
__device__ __forceinline__ void ldm_x4(uint32_t* r, uint32_t addr) {
    asm volatile("ldmatrix.sync.aligned.m8n8.x4.shared.b16 {%0,%1,%2,%3}, [%4];"
        : "=r"(r[0]), "=r"(r[1]), "=r"(r[2]), "=r"(r[3]) : "r"(addr));
}
__device__ __forceinline__ void mma_f16(float* d, const uint32_t* a, const uint32_t* b) {
    asm volatile(
        "mma.sync.aligned.m16n8k16.row.col.f32.f16.f16.f32 "
        "{%0,%1,%2,%3}, {%4,%5,%6,%7}, {%8,%9}, {%0,%1,%2,%3};"
        : "+f"(d[0]), "+f"(d[1]), "+f"(d[2]), "+f"(d[3])
        : "r"(a[0]), "r"(a[1]), "r"(a[2]), "r"(a[3]), "r"(b[0]), "r"(b[1]));
}

// ============================================================================
// One fused convert kernel: all weights -> fp16, x -> fp16 hi/lo.
// ============================================================================
#define N4_X   (L_SEQ * DM / 4)
#define N4_WIN (2 * DI * DM / 4)
#define N4_WX  (NPROJ * DI / 4)
#define N4_WO  (DM * DI / 4)
#define N4_TOT (N4_X + N4_WIN + N4_WX + N4_WO)

__global__ __launch_bounds__(256)
void cvt_all(const float* __restrict__ x, const float* __restrict__ W_in,
             const float* __restrict__ W_x, const float* __restrict__ W_out)
{
    int i = blockIdx.x * blockDim.x + threadIdx.x;
    if (i >= N4_TOT) return;

    if (i < N4_X) {
        float4 v = ((const float4*)x)[i];
        __half hx = __float2half_rn(v.x), hy = __float2half_rn(v.y);
        __half hz = __float2half_rn(v.z), hw = __float2half_rn(v.w);
        ((__half2*)g_ahi)[i*2+0] = __half2(hx, hy);
        ((__half2*)g_ahi)[i*2+1] = __half2(hz, hw);
        ((__half2*)g_alo)[i*2+0] = __half2(__float2half_rn(v.x - __half2float(hx)),
                                           __float2half_rn(v.y - __half2float(hy)));
        ((__half2*)g_alo)[i*2+1] = __half2(__float2half_rn(v.z - __half2float(hz)),
                                           __float2half_rn(v.w - __half2float(hw)));
        return;
    }
    const float* src; __half* dst; int j;
    if (i < N4_X + N4_WIN)              { j = i - N4_X;                  src = W_in;  dst = g_win_h; }
    else if (i < N4_X + N4_WIN + N4_WX) { j = i - N4_X - N4_WIN;         src = W_x;   dst = g_wx_h; }
    else                                { j = i - N4_X - N4_WIN - N4_WX; src = W_out; dst = g_wout_h; }
    float4 v = ((const float4*)src)[j];
    ((__half2*)dst)[j*2+0] = __half2(__float2half_rn(v.x), __float2half_rn(v.y));
    ((__half2*)dst)[j*2+1] = __half2(__float2half_rn(v.z), __float2half_rn(v.w));
}

// ============================================================================
// fp16 2-term emulated-fp32 GEMM via mma.sync m16n8k16.
// Block 128x128, BK=64, 8 warps (4M x 2N). 2-stage ring, 1 barrier/stage.
// Per k16: 8 LDSM up-front, then 16 independent ah-MMAs, then 16 al-MMAs
// (dependent partner is 16 instructions back -> HMMA latency covered).
// ============================================================================
#define ROWB  144
#define MATB  (128 * ROWB)
#define BUFB  (3 * MATB)
#define GEMM_SMEM (2 * BUFB)   // 110592

__device__ __forceinline__ void gemm_load_stage(
    uint32_t sb, int buf, int k0,
    const __half* __restrict__ Ahi, const __half* __restrict__ Alo,
    const __half* __restrict__ Wh,
    int m0, int n0, int Nc, int Kd, int tid)
{
    uint32_t base = sb + buf * BUFB;
#pragma unroll
    for (int it = 0; it < 12; it++) {
        int q   = tid + it * 256;
        int mat = q >> 10;
        int rem = q & 1023;
        int row = rem >> 3;
        int ch  = rem & 7;
        uint32_t dst = base + mat * MATB + row * ROWB + ch * 16;
        const __half* src;
        if (mat < 2) {
            const __half* bp = (mat == 0) ? Ahi : Alo;
            src = bp + (size_t)(m0 + row) * Kd + k0 + ch * 8;
        } else {
            int wr = n0 + row; if (wr >= Nc) wr = Nc - 1;
            src = Wh + (size_t)wr * Kd + k0 + ch * 8;
        }
        cp_async16(dst, src);
    }
    cp_commit();
}

template<int ACT>
__global__ __launch_bounds__(256, 2)
void gemm_mma(const __half* __restrict__ Ahi, const __half* __restrict__ Alo,
              const __half* __restrict__ Wh,
              const float* __restrict__ bias, float* __restrict__ C,
              int Nc, int Kd, int ldc)
{
    extern __shared__ char smraw[];
    uint32_t sb = smem_u32(smraw);

    int tid  = threadIdx.x;
    int wid  = tid >> 5;
    int lane = tid & 31;
    int wm   = wid & 3;
    int wn   = wid >> 2;
    int m0 = blockIdx.y * 128;
    int n0 = blockIdx.x * 128;

    float acc[2][8][4];
#pragma unroll
    for (int i = 0; i < 2; i++)
#pragma unroll
        for (int j = 0; j < 8; j++)
#pragma unroll
            for (int k = 0; k < 4; k++) acc[i][j][k] = 0.f;

    int aRow = wm * 32 + (lane & 15);
    int aColHalf = (lane >> 4) << 3;
    int bRow = wn * 64 + ((lane >> 4) & 1) * 8 + (lane & 7);
    int bColHalf = ((lane >> 3) & 1) << 3;

    const int NSTAGE = Kd / 64;
    gemm_load_stage(sb, 0, 0, Ahi, Alo, Wh, m0, n0, Nc, Kd, tid);

    int buf = 0;
    for (int s = 0; s < NSTAGE; s++) {
        cp_wait<0>();
        __syncthreads();
        if (s + 1 < NSTAGE)
            gemm_load_stage(sb, buf ^ 1, (s + 1) * 64, Ahi, Alo, Wh, m0, n0, Nc, Kd, tid);

        uint32_t bA = sb + buf * BUFB;
        uint32_t bW = bA + 2 * MATB;
#pragma unroll
        for (int kc = 0; kc < 4; kc++) {
            int acol2 = (kc * 16 + aColHalf) * 2;
            int bcol2 = (kc * 16 + bColHalf) * 2;
            uint32_t ah[2][4], al[2][4], bh[4][4];
#pragma unroll
            for (int mt = 0; mt < 2; mt++) {
                uint32_t off = (uint32_t)((aRow + mt * 16) * ROWB + acol2);
                ldm_x4(ah[mt], bA + off);
                ldm_x4(al[mt], bA + MATB + off);
            }
#pragma unroll
            for (int ntp = 0; ntp < 4; ntp++) {
                uint32_t off = (uint32_t)((bRow + ntp * 16) * ROWB + bcol2);
                ldm_x4(bh[ntp], bW + off);
            }
            // block 1: 16 MMAs on 16 DISTINCT accumulators (independent)
#pragma unroll
            for (int ntp = 0; ntp < 4; ntp++) {
#pragma unroll
                for (int mt = 0; mt < 2; mt++) {
                    mma_f16(acc[mt][2*ntp+0], ah[mt], bh[ntp] + 0);
                    mma_f16(acc[mt][2*ntp+1], ah[mt], bh[ntp] + 2);
                }
            }
            // block 2: the lo-term partners, each 16 instructions after its
            // dependency -> HMMA latency fully covered
#pragma unroll
            for (int ntp = 0; ntp < 4; ntp++) {
#pragma unroll
                for (int mt = 0; mt < 2; mt++) {
                    mma_f16(acc[mt][2*ntp+0], al[mt], bh[ntp] + 0);
                    mma_f16(acc[mt][2*ntp+1], al[mt], bh[ntp] + 2);
                }
            }
        }
        buf ^= 1;
    }

#pragma unroll
    for (int mt = 0; mt < 2; mt++) {
        int r0 = m0 + wm * 32 + mt * 16 + (lane >> 2);
#pragma unroll
        for (int nt = 0; nt < 8; nt++) {
            int c = n0 + wn * 64 + nt * 8 + 2 * (lane & 3);
            if (c < Nc) {
                float b0 = bias[c], b1 = bias[c + 1];
                float v0 = acc[mt][nt][0] + b0;
                float v1 = acc[mt][nt][1] + b1;
                float v2 = acc[mt][nt][2] + b0;
                float v3 = acc[mt][nt][3] + b1;
                if (ACT == 1) {
                    if (c     < DI) { v0 = softplus_f(v0); v2 = softplus_f(v2); }
                    if (c + 1 < DI) { v1 = softplus_f(v1); v3 = softplus_f(v3); }
                }
                *(float2*)&C[(size_t)r0 * ldc + c]       = make_float2(v0, v1);
                *(float2*)&C[(size_t)(r0 + 8) * ldc + c] = make_float2(v2, v3);
            }
        }
    }
}

// ============================================================================
// Depthwise causal conv (K=4) + silu, 4 channels/thread.
// ============================================================================
__global__ __launch_bounds__(256)
void conv_silu_k(const float* __restrict__ Wc, const float* __restrict__ bc)
{
    int idx = blockIdx.x * blockDim.x + threadIdx.x;
    int t  = idx >> 9;
    int d4 = (idx & 511) << 2;

    float4 acc = *(const float4*)&bc[d4];
#pragma unroll
    for (int k = 0; k < KC; k++) {
        int tt = t - (KC - 1) + k;
        if (tt >= 0) {
            float4 v = *(const float4*)&g_xr[(size_t)tt * (2 * DI) + d4];
            acc.x = fmaf(Wc[(d4 + 0) * KC + k], v.x, acc.x);
            acc.y = fmaf(Wc[(d4 + 1) * KC + k], v.y, acc.y);
            acc.z = fmaf(Wc[(d4 + 2) * KC + k], v.z, acc.z);
            acc.w = fmaf(Wc[(d4 + 3) * KC + k], v.w, acc.w);
        }
    }
    float s0 = acc.x / (1.f + __expf(-acc.x));
    float s1 = acc.y / (1.f + __expf(-acc.y));
    float s2 = acc.z / (1.f + __expf(-acc.z));
    float s3 = acc.w / (1.f + __expf(-acc.w));
    size_t o = (size_t)t * DI + d4;
    *(float4*)&g_xi[o] = make_float4(s0, s1, s2, s3);
    __half h0 = __float2half_rn(s0), h1 = __float2half_rn(s1);
    __half h2 = __float2half_rn(s2), h3 = __float2half_rn(s3);
    *(__half2*)&g_ahi[o]     = __half2(h0, h1);
    *(__half2*)&g_ahi[o + 2] = __half2(h2, h3);
    *(__half2*)&g_alo[o]     = __half2(__float2half_rn(s0 - __half2float(h0)),
                                       __float2half_rn(s1 - __half2float(h1)));
    *(__half2*)&g_alo[o + 2] = __half2(__float2half_rn(s2 - __half2float(h2)),
                                       __float2half_rn(s3 - __half2float(h3)));
}

// ============================================================================
// Chunked selective scan (unchanged numerics).
// ============================================================================
__global__ __launch_bounds__(256, 1)
void scan_p1(const float* __restrict__ A_log)
{
    __shared__ float s_delta[2][TT][SD];
    __shared__ float s_xi   [2][TT][SD];
    __shared__ float s_B    [2][TT][NST];

    int tid = threadIdx.x;
    int nq = tid & 3;
    int dl = tid >> 2;
    int dbase = blockIdx.x * SD;
    int d = dbase + dl;
    int chunk = blockIdx.y;
    int tbase = chunk * CH;

    float4 alv = *(const float4*)&A_log[d * NST + nq * 4];
    float A0 = -__expf(alv.x), A1 = -__expf(alv.y);
    float A2 = -__expf(alv.z), A3 = -__expf(alv.w);

    float ap0 = 1.f, ap1 = 1.f, ap2 = 1.f, ap3 = 1.f;
    float h0 = 0.f, h1 = 0.f, h2 = 0.f, h3 = 0.f;

    auto issue = [&](int t0, int buf) {
        for (int q = tid; q < 576; q += 256) {
            if (q < 512) {
                int arr = q >> 8;
                int rem = q & 255;
                int tq  = rem >> 4;
                int v   = (rem & 15) * 4;
                int t   = tbase + t0 + tq;
                if (arr == 0)
                    cp_async16p(&s_delta[buf][tq][v], g_proj + (size_t)t * NPROJ + dbase + v);
                else
                    cp_async16p(&s_xi[buf][tq][v], g_xi + (size_t)t * DI + dbase + v);
            } else {
                int rem = q - 512;
                int tq  = rem >> 2;
                int v   = (rem & 3) * 4;
                int t   = tbase + t0 + tq;
                cp_async16p(&s_B[buf][tq][v], g_proj + (size_t)t * NPROJ + DI + v);
            }
        }
        cp_commit();
    };

    issue(0, 0);
    int buf = 0;
    const int NT = CH / TT;
    for (int it = 0; it < NT; it++) {
        if (it + 1 < NT) { issue((it + 1) * TT, buf ^ 1); cp_wait<1>(); }
        else             { cp_wait<0>(); }
        __syncthreads();
#pragma unroll
        for (int tt = 0; tt < TT; tt++) {
            float del = s_delta[buf][tt][dl];
            float xv  = s_xi[buf][tt][dl];
            float4 bv = *(const float4*)&s_B[buf][tt][nq * 4];
            float dx = del * xv;
            float e0 = __expf(del * A0), e1 = __expf(del * A1);
            float e2 = __expf(del * A2), e3 = __expf(del * A3);
            ap0 *= e0; ap1 *= e1; ap2 *= e2; ap3 *= e3;
            h0 = fmaf(e0, h0, dx * bv.x);
            h1 = fmaf(e1, h1, dx * bv.y);
            h2 = fmaf(e2, h2, dx * bv.z);
            h3 = fmaf(e3, h3, dx * bv.w);
        }
        __syncthreads();
        buf ^= 1;
    }
    int idx = (chunk * DI + d) * NST + nq * 4;
    *(float4*)&g_cA[idx] = make_float4(ap0, ap1, ap2, ap3);
    *(float4*)&g_cB[idx] = make_float4(h0, h1, h2, h3);
}

__global__ __launch_bounds__(256)
void scan_comb()
{
    int dn = blockIdx.x * blockDim.x + threadIdx.x;
    float h = 0.f;
#pragma unroll
    for (int c = 0; c < NCH; c++) {
        int idx = c * (DI * NST) + dn;
        g_h0[idx] = h;
        h = fmaf(g_cA[idx], h, g_cB[idx]);
    }
}

__global__ __launch_bounds__(256, 1)
void scan_p3(const float* __restrict__ A_log, const float* __restrict__ Dv)
{
    __shared__ float s_delta[2][TT][SD];
    __shared__ float s_xi   [2][TT][SD];
    __shared__ float s_res  [2][TT][SD];
    __shared__ float s_B    [2][TT][NST];
    __shared__ float s_C    [2][TT][NST];

    int tid = threadIdx.x;
    int nq = tid & 3;
    int dl = tid >> 2;
    int dbase = blockIdx.x * SD;
    int d = dbase + dl;
    int chunk = blockIdx.y;
    int tbase = chunk * CH;

    float4 alv = *(const float4*)&A_log[d * NST + nq * 4];
    float A0 = -__expf(alv.x), A1 = -__expf(alv.y);
    float A2 = -__expf(alv.z), A3 = -__expf(alv.w);
    float Dd = Dv[d];

    float4 hv = *(const float4*)&g_h0[(chunk * DI + d) * NST + nq * 4];
    float h0 = hv.x, h1 = hv.y, h2 = hv.z, h3 = hv.w;

    auto issue = [&](int t0, int buf) {
        for (int q = tid; q < 896; q += 256) {
            if (q < 768) {
                int arr = q >> 8;
                int rem = q & 255;
                int tq  = rem >> 4;
                int v   = (rem & 15) * 4;
                int t   = tbase + t0 + tq;
                if      (arr == 0) cp_async16p(&s_delta[buf][tq][v], g_proj + (size_t)t * NPROJ + dbase + v);
                else if (arr == 1) cp_async16p(&s_xi[buf][tq][v],    g_xi   + (size_t)t * DI + dbase + v);
                else               cp_async16p(&s_res[buf][tq][v],   g_xr   + (size_t)t * (2*DI) + DI + dbase + v);
            } else {
                int rem = q - 768;
                int arr = rem >> 6;
                int r2  = rem & 63;
                int tq  = r2 >> 2;
                int v   = (r2 & 3) * 4;
                int t   = tbase + t0 + tq;
                if (arr == 0) cp_async16p(&s_B[buf][tq][v], g_proj + (size_t)t * NPROJ + DI + v);
                else          cp_async16p(&s_C[buf][tq][v], g_proj + (size_t)t * NPROJ + DI + NST + v);
            }
        }
        cp_commit();
    };

    issue(0, 0);
    int buf = 0;
    const int NT = CH / TT;
    for (int it = 0; it < NT; it++) {
        if (it + 1 < NT) { issue((it + 1) * TT, buf ^ 1); cp_wait<1>(); }
        else             { cp_wait<0>(); }
        __syncthreads();

        int t0 = tbase + it * TT;
#pragma unroll
        for (int tt = 0; tt < TT; tt++) {
            float del = s_delta[buf][tt][dl];
            float xv  = s_xi[buf][tt][dl];
            float4 bv = *(const float4*)&s_B[buf][tt][nq * 4];
            float4 cv = *(const float4*)&s_C[buf][tt][nq * 4];
            float dx = del * xv;
            float e0 = __expf(del * A0), e1 = __expf(del * A1);
            float e2 = __expf(del * A2), e3 = __expf(del * A3);
            h0 = fmaf(e0, h0, dx * bv.x);
            h1 = fmaf(e1, h1, dx * bv.y);
            h2 = fmaf(e2, h2, dx * bv.z);
            h3 = fmaf(e3, h3, dx * bv.w);
            float yv = h0 * cv.x;
            yv = fmaf(h1, cv.y, yv);
            yv = fmaf(h2, cv.z, yv);
            yv = fmaf(h3, cv.w, yv);
            yv += __shfl_xor_sync(0xffffffffu, yv, 1);
            yv += __shfl_xor_sync(0xffffffffu, yv, 2);
            if (nq == 0) {
                float r  = s_res[buf][tt][dl];
                float y  = fmaf(xv, Dd, yv);
                float zv = y * (r / (1.f + __expf(-r)));
                size_t o = (size_t)(t0 + tt) * DI + d;
                __half zh = __float2half_rn(zv);
                g_ahi[o] = zh;
                g_alo[o] = __float2half_rn(zv - __half2float(zh));
            }
        }
        __syncthreads();
        buf ^= 1;
    }
}

// ============================================================================
// launch
// ============================================================================
extern "C" void kernel_launch(void* const* d_in, const int* in_sizes, int n_in,
                              void* d_out, int out_size)
{
    const float* x      = (const float*)d_in[0];
    const float* W_in   = (const float*)d_in[1];
    const float* b_in   = (const float*)d_in[2];
    const float* W_conv = (const float*)d_in[3];
    const float* b_conv = (const float*)d_in[4];
    const float* W_x    = (const float*)d_in[5];
    const float* b_x    = (const float*)d_in[6];
    const float* W_out  = (const float*)d_in[7];
    const float* b_out  = (const float*)d_in[8];
    const float* A_log  = (const float*)d_in[9];
    const float* Dv     = (const float*)d_in[10];
    float* out = (float*)d_out;

    float *xr, *proj;
    __half *ahi, *alo, *win_h, *wx_h, *wout_h;
    cudaGetSymbolAddress((void**)&xr,     g_xr);
    cudaGetSymbolAddress((void**)&proj,   g_proj);
    cudaGetSymbolAddress((void**)&ahi,    g_ahi);
    cudaGetSymbolAddress((void**)&alo,    g_alo);
    cudaGetSymbolAddress((void**)&win_h,  g_win_h);
    cudaGetSymbolAddress((void**)&wx_h,   g_wx_h);
    cudaGetSymbolAddress((void**)&wout_h, g_wout_h);

    static bool attr_done = false;
    if (!attr_done) {
        cudaFuncSetAttribute(gemm_mma<0>, cudaFuncAttributeMaxDynamicSharedMemorySize, GEMM_SMEM);
        cudaFuncSetAttribute(gemm_mma<1>, cudaFuncAttributeMaxDynamicSharedMemorySize, GEMM_SMEM);
        attr_done = true;
    }

    cvt_all<<<(N4_TOT + 255) / 256, 256>>>(x, W_in, W_x, W_out);

    {   // GEMM1: xr = x @ W_in.T + b_in
        dim3 grid((2 * DI) / 128, L_SEQ / 128);
        gemm_mma<0><<<grid, 256, GEMM_SMEM>>>(ahi, alo, win_h, b_in, xr,
                                              2 * DI, DM, 2 * DI);
    }
    conv_silu_k<<<(L_SEQ * DI / 4) / 256, 256>>>(W_conv, b_conv);

    {   // GEMM2: proj = xi @ W_x.T + b_x (softplus on delta)
        dim3 grid((NPROJ + 127) / 128, L_SEQ / 128);
        gemm_mma<1><<<grid, 256, GEMM_SMEM>>>(ahi, alo, wx_h, b_x, proj,
                                              NPROJ, DI, NPROJ);
    }
    {   // chunked scan
        dim3 g1(DI / SD, NCH);
        scan_p1<<<g1, 256>>>(A_log);
        scan_comb<<<(DI * NST) / 256, 256>>>();
        scan_p3<<<g1, 256>>>(A_log, Dv);
    }
    {   // GEMM3: out = z @ W_out.T + b_out
        dim3 grid(DM / 128, L_SEQ / 128);
        gemm_mma<0><<<grid, 256, GEMM_SMEM>>>(ahi, alo, wout_h, b_out, out,
                                              DM, DI, DM);
    }
}

// round 9
// speedup vs baseline: 1.2429x; 1.2429x over previous
#include <cuda_runtime.h>
#include <cuda_fp16.h>
#include <math.h>
#include <stdint.h>

// ---------------- problem constants ----------------
#define L_SEQ 2048
#define DM    1024
#define DI    2048
#define NST   16
#define KC    4
#define NPROJ (DI + 2*NST)   // 2080

#define NCH   16
#define CH    128
#define TT    16
#define SD    64

// ---------------- scratch (device globals) ----------------
__device__ float g_xr  [L_SEQ * 2 * DI];
__device__ float g_xi  [L_SEQ * DI];
__device__ float g_proj[L_SEQ * NPROJ];

__device__ __half g_ahi[L_SEQ * DI];
__device__ __half g_alo[L_SEQ * DI];
__device__ __half g_win_h [2 * DI * DM];
__device__ __half g_wx_h  [NPROJ * DI];
__device__ __half g_wout_h[DM * DI];

__device__ float g_cA[NCH * DI * NST];
__device__ float g_cB[NCH * DI * NST];
__device__ float g_h0[NCH * DI * NST];

__device__ __forceinline__ float softplus_f(float x) {
    return fmaxf(x, 0.f) + log1pf(expf(-fabsf(x)));
}

// ---------------- PTX helpers ----------------
__device__ __forceinline__ uint32_t smem_u32(const void* p) {
    uint32_t a;
    asm("{ .reg .u64 t; cvta.to.shared.u64 t, %1; cvt.u32.u64 %0, t; }" : "=r"(a) : "l"(p));
    return a;
}
__device__ __forceinline__ void cp_async16(uint32_t sm, const void* gm) {
    asm volatile("cp.async.ca.shared.global [%0], [%1], 16;" :: "r"(sm), "l"(gm));
}
__device__ __forceinline__ void cp_async16p(void* sm, const void* gm) {
    cp_async16(smem_u32(sm), gm);
}
__device__ __forceinline__ void cp_commit() { asm volatile("cp.async.commit_group;"); }
template<int N> __device__ __forceinline__ void cp_wait() {
    asm volatile("cp.async.wait_group %0;" :: "n"(N));
}
__device__ __forceinline__ void ldm_x4(uint32_t* r, uint32_t addr) {
    asm volatile("ldmatrix.sync.aligned.m8n8.x4.shared.b16 {%0,%1,%2,%3}, [%4];"
        : "=r"(r[0]), "=r"(r[1]), "=r"(r[2]), "=r"(r[3]) : "r"(addr));
}
__device__ __forceinline__ void mma_f16(float* d, const uint32_t* a, const uint32_t* b) {
    asm volatile(
        "mma.sync.aligned.m16n8k16.row.col.f32.f16.f16.f32 "
        "{%0,%1,%2,%3}, {%4,%5,%6,%7}, {%8,%9}, {%0,%1,%2,%3};"
        : "+f"(d[0]), "+f"(d[1]), "+f"(d[2]), "+f"(d[3])
        : "r"(a[0]), "r"(a[1]), "r"(a[2]), "r"(a[3]), "r"(b[0]), "r"(b[1]));
}

// ============================================================================
// One fused convert kernel: weights -> fp16; x -> fp16 hi ONLY (GEMM1 is
// now single-term, so x-lo is never read).
// ============================================================================
#define N4_X   (L_SEQ * DM / 4)
#define N4_WIN (2 * DI * DM / 4)
#define N4_WX  (NPROJ * DI / 4)
#define N4_WO  (DM * DI / 4)
#define N4_TOT (N4_X + N4_WIN + N4_WX + N4_WO)

__global__ __launch_bounds__(256)
void cvt_all(const float* __restrict__ x, const float* __restrict__ W_in,
             const float* __restrict__ W_x, const float* __restrict__ W_out)
{
    int i = blockIdx.x * blockDim.x + threadIdx.x;
    if (i >= N4_TOT) return;

    const float* src; __half* dst; int j;
    if (i < N4_X)                       { j = i;                         src = x;     dst = g_ahi; }
    else if (i < N4_X + N4_WIN)         { j = i - N4_X;                  src = W_in;  dst = g_win_h; }
    else if (i < N4_X + N4_WIN + N4_WX) { j = i - N4_X - N4_WIN;         src = W_x;   dst = g_wx_h; }
    else                                { j = i - N4_X - N4_WIN - N4_WX; src = W_out; dst = g_wout_h; }
    float4 v = ((const float4*)src)[j];
    ((__half2*)dst)[j*2+0] = __half2(__float2half_rn(v.x), __float2half_rn(v.y));
    ((__half2*)dst)[j*2+1] = __half2(__float2half_rn(v.z), __float2half_rn(v.w));
}

// ============================================================================
// fp16 GEMM via mma.sync m16n8k16, templated on number of A terms.
//   NT=2: C = (Ahi+Alo) @ Wh^T  (emulated-fp32 A)
//   NT=1: C =  Ahi      @ Wh^T  (plain fp16 A; half the MMAs + smem)
// Block 128x128, BK=64, 8 warps (4M x 2N). 2-stage ring, 1 barrier/stage.
// ============================================================================
#define ROWB  144
#define MATB  (128 * ROWB)
#define GEMM_SMEM_NT(NT) (2 * ((NT) + 1) * MATB)   // NT=2: 110592, NT=1: 73728

template<int NT>
__device__ __forceinline__ void gemm_load_stage(
    uint32_t sb, int buf, int k0,
    const __half* __restrict__ Ahi, const __half* __restrict__ Alo,
    const __half* __restrict__ Wh,
    int m0, int n0, int Nc, int Kd, int tid)
{
    uint32_t base = sb + buf * ((NT + 1) * MATB);
#pragma unroll
    for (int it = 0; it < 4 * (NT + 1); it++) {
        int q   = tid + it * 256;
        int mat = q >> 10;         // 0..NT
        int rem = q & 1023;
        int row = rem >> 3;
        int ch  = rem & 7;
        uint32_t dst = base + mat * MATB + row * ROWB + ch * 16;
        const __half* src;
        if (mat < NT) {
            const __half* bp = (mat == 0) ? Ahi : Alo;
            src = bp + (size_t)(m0 + row) * Kd + k0 + ch * 8;
        } else {
            int wr = n0 + row; if (wr >= Nc) wr = Nc - 1;
            src = Wh + (size_t)wr * Kd + k0 + ch * 8;
        }
        cp_async16(dst, src);
    }
    cp_commit();
}

template<int ACT, int NT>
__global__ __launch_bounds__(256, 2)
void gemm_mma(const __half* __restrict__ Ahi, const __half* __restrict__ Alo,
              const __half* __restrict__ Wh,
              const float* __restrict__ bias, float* __restrict__ C,
              int Nc, int Kd, int ldc)
{
    extern __shared__ char smraw[];
    uint32_t sb = smem_u32(smraw);

    int tid  = threadIdx.x;
    int wid  = tid >> 5;
    int lane = tid & 31;
    int wm   = wid & 3;
    int wn   = wid >> 2;
    int m0 = blockIdx.y * 128;
    int n0 = blockIdx.x * 128;

    float acc[2][8][4];
#pragma unroll
    for (int i = 0; i < 2; i++)
#pragma unroll
        for (int j = 0; j < 8; j++)
#pragma unroll
            for (int k = 0; k < 4; k++) acc[i][j][k] = 0.f;

    int aRow = wm * 32 + (lane & 15);
    int aColHalf = (lane >> 4) << 3;
    int bRow = wn * 64 + ((lane >> 4) & 1) * 8 + (lane & 7);
    int bColHalf = ((lane >> 3) & 1) << 3;

    const int NSTAGE = Kd / 64;
    gemm_load_stage<NT>(sb, 0, 0, Ahi, Alo, Wh, m0, n0, Nc, Kd, tid);

    int buf = 0;
    for (int s = 0; s < NSTAGE; s++) {
        cp_wait<0>();
        __syncthreads();
        if (s + 1 < NSTAGE)
            gemm_load_stage<NT>(sb, buf ^ 1, (s + 1) * 64, Ahi, Alo, Wh, m0, n0, Nc, Kd, tid);

        uint32_t bA = sb + buf * ((NT + 1) * MATB);
        uint32_t bW = bA + NT * MATB;
#pragma unroll
        for (int kc = 0; kc < 4; kc++) {
            int acol2 = (kc * 16 + aColHalf) * 2;
            int bcol2 = (kc * 16 + bColHalf) * 2;
            uint32_t ah[2][4], al[2][4], bh[4][4];
#pragma unroll
            for (int mt = 0; mt < 2; mt++) {
                uint32_t off = (uint32_t)((aRow + mt * 16) * ROWB + acol2);
                ldm_x4(ah[mt], bA + off);
                if (NT == 2) ldm_x4(al[mt], bA + MATB + off);
            }
#pragma unroll
            for (int ntp = 0; ntp < 4; ntp++) {
                uint32_t off = (uint32_t)((bRow + ntp * 16) * ROWB + bcol2);
                ldm_x4(bh[ntp], bW + off);
            }
#pragma unroll
            for (int ntp = 0; ntp < 4; ntp++) {
#pragma unroll
                for (int mt = 0; mt < 2; mt++) {
                    mma_f16(acc[mt][2*ntp+0], ah[mt], bh[ntp] + 0);
                    mma_f16(acc[mt][2*ntp+1], ah[mt], bh[ntp] + 2);
                }
            }
            if (NT == 2) {
#pragma unroll
                for (int ntp = 0; ntp < 4; ntp++) {
#pragma unroll
                    for (int mt = 0; mt < 2; mt++) {
                        mma_f16(acc[mt][2*ntp+0], al[mt], bh[ntp] + 0);
                        mma_f16(acc[mt][2*ntp+1], al[mt], bh[ntp] + 2);
                    }
                }
            }
        }
        buf ^= 1;
    }

#pragma unroll
    for (int mt = 0; mt < 2; mt++) {
        int r0 = m0 + wm * 32 + mt * 16 + (lane >> 2);
#pragma unroll
        for (int nt = 0; nt < 8; nt++) {
            int c = n0 + wn * 64 + nt * 8 + 2 * (lane & 3);
            if (c < Nc) {
                float b0 = bias[c], b1 = bias[c + 1];
                float v0 = acc[mt][nt][0] + b0;
                float v1 = acc[mt][nt][1] + b1;
                float v2 = acc[mt][nt][2] + b0;
                float v3 = acc[mt][nt][3] + b1;
                if (ACT == 1) {
                    if (c     < DI) { v0 = softplus_f(v0); v2 = softplus_f(v2); }
                    if (c + 1 < DI) { v1 = softplus_f(v1); v3 = softplus_f(v3); }
                }
                *(float2*)&C[(size_t)r0 * ldc + c]       = make_float2(v0, v1);
                *(float2*)&C[(size_t)(r0 + 8) * ldc + c] = make_float2(v2, v3);
            }
        }
    }
}

// ============================================================================
// Depthwise causal conv (K=4) + silu, 4 channels/thread.
// Writes fp32 xi AND fp16 hi/lo (GEMM2 is 2-term).
// ============================================================================
__global__ __launch_bounds__(256)
void conv_silu_k(const float* __restrict__ Wc, const float* __restrict__ bc)
{
    int idx = blockIdx.x * blockDim.x + threadIdx.x;
    int t  = idx >> 9;
    int d4 = (idx & 511) << 2;

    float4 acc = *(const float4*)&bc[d4];
#pragma unroll
    for (int k = 0; k < KC; k++) {
        int tt = t - (KC - 1) + k;
        if (tt >= 0) {
            float4 v = *(const float4*)&g_xr[(size_t)tt * (2 * DI) + d4];
            acc.x = fmaf(Wc[(d4 + 0) * KC + k], v.x, acc.x);
            acc.y = fmaf(Wc[(d4 + 1) * KC + k], v.y, acc.y);
            acc.z = fmaf(Wc[(d4 + 2) * KC + k], v.z, acc.z);
            acc.w = fmaf(Wc[(d4 + 3) * KC + k], v.w, acc.w);
        }
    }
    float s0 = acc.x / (1.f + __expf(-acc.x));
    float s1 = acc.y / (1.f + __expf(-acc.y));
    float s2 = acc.z / (1.f + __expf(-acc.z));
    float s3 = acc.w / (1.f + __expf(-acc.w));
    size_t o = (size_t)t * DI + d4;
    *(float4*)&g_xi[o] = make_float4(s0, s1, s2, s3);
    __half h0 = __float2half_rn(s0), h1 = __float2half_rn(s1);
    __half h2 = __float2half_rn(s2), h3 = __float2half_rn(s3);
    *(__half2*)&g_ahi[o]     = __half2(h0, h1);
    *(__half2*)&g_ahi[o + 2] = __half2(h2, h3);
    *(__half2*)&g_alo[o]     = __half2(__float2half_rn(s0 - __half2float(h0)),
                                       __float2half_rn(s1 - __half2float(h1)));
    *(__half2*)&g_alo[o + 2] = __half2(__float2half_rn(s2 - __half2float(h2)),
                                       __float2half_rn(s3 - __half2float(h3)));
}

// ============================================================================
// Chunked selective scan (numerics unchanged; p3 writes hi only — GEMM3
// is single-term now).
// ============================================================================
__global__ __launch_bounds__(256, 1)
void scan_p1(const float* __restrict__ A_log)
{
    __shared__ float s_delta[2][TT][SD];
    __shared__ float s_xi   [2][TT][SD];
    __shared__ float s_B    [2][TT][NST];

    int tid = threadIdx.x;
    int nq = tid & 3;
    int dl = tid >> 2;
    int dbase = blockIdx.x * SD;
    int d = dbase + dl;
    int chunk = blockIdx.y;
    int tbase = chunk * CH;

    float4 alv = *(const float4*)&A_log[d * NST + nq * 4];
    float A0 = -__expf(alv.x), A1 = -__expf(alv.y);
    float A2 = -__expf(alv.z), A3 = -__expf(alv.w);

    float ap0 = 1.f, ap1 = 1.f, ap2 = 1.f, ap3 = 1.f;
    float h0 = 0.f, h1 = 0.f, h2 = 0.f, h3 = 0.f;

    auto issue = [&](int t0, int buf) {
        for (int q = tid; q < 576; q += 256) {
            if (q < 512) {
                int arr = q >> 8;
                int rem = q & 255;
                int tq  = rem >> 4;
                int v   = (rem & 15) * 4;
                int t   = tbase + t0 + tq;
                if (arr == 0)
                    cp_async16p(&s_delta[buf][tq][v], g_proj + (size_t)t * NPROJ + dbase + v);
                else
                    cp_async16p(&s_xi[buf][tq][v], g_xi + (size_t)t * DI + dbase + v);
            } else {
                int rem = q - 512;
                int tq  = rem >> 2;
                int v   = (rem & 3) * 4;
                int t   = tbase + t0 + tq;
                cp_async16p(&s_B[buf][tq][v], g_proj + (size_t)t * NPROJ + DI + v);
            }
        }
        cp_commit();
    };

    issue(0, 0);
    int buf = 0;
    const int NT2 = CH / TT;
    for (int it = 0; it < NT2; it++) {
        if (it + 1 < NT2) { issue((it + 1) * TT, buf ^ 1); cp_wait<1>(); }
        else              { cp_wait<0>(); }
        __syncthreads();
#pragma unroll
        for (int tt = 0; tt < TT; tt++) {
            float del = s_delta[buf][tt][dl];
            float xv  = s_xi[buf][tt][dl];
            float4 bv = *(const float4*)&s_B[buf][tt][nq * 4];
            float dx = del * xv;
            float e0 = __expf(del * A0), e1 = __expf(del * A1);
            float e2 = __expf(del * A2), e3 = __expf(del * A3);
            ap0 *= e0; ap1 *= e1; ap2 *= e2; ap3 *= e3;
            h0 = fmaf(e0, h0, dx * bv.x);
            h1 = fmaf(e1, h1, dx * bv.y);
            h2 = fmaf(e2, h2, dx * bv.z);
            h3 = fmaf(e3, h3, dx * bv.w);
        }
        __syncthreads();
        buf ^= 1;
    }
    int idx = (chunk * DI + d) * NST + nq * 4;
    *(float4*)&g_cA[idx] = make_float4(ap0, ap1, ap2, ap3);
    *(float4*)&g_cB[idx] = make_float4(h0, h1, h2, h3);
}

__global__ __launch_bounds__(256)
void scan_comb()
{
    int dn = blockIdx.x * blockDim.x + threadIdx.x;
    float h = 0.f;
#pragma unroll
    for (int c = 0; c < NCH; c++) {
        int idx = c * (DI * NST) + dn;
        g_h0[idx] = h;
        h = fmaf(g_cA[idx], h, g_cB[idx]);
    }
}

__global__ __launch_bounds__(256, 1)
void scan_p3(const float* __restrict__ A_log, const float* __restrict__ Dv)
{
    __shared__ float s_delta[2][TT][SD];
    __shared__ float s_xi   [2][TT][SD];
    __shared__ float s_res  [2][TT][SD];
    __shared__ float s_B    [2][TT][NST];
    __shared__ float s_C    [2][TT][NST];

    int tid = threadIdx.x;
    int nq = tid & 3;
    int dl = tid >> 2;
    int dbase = blockIdx.x * SD;
    int d = dbase + dl;
    int chunk = blockIdx.y;
    int tbase = chunk * CH;

    float4 alv = *(const float4*)&A_log[d * NST + nq * 4];
    float A0 = -__expf(alv.x), A1 = -__expf(alv.y);
    float A2 = -__expf(alv.z), A3 = -__expf(alv.w);
    float Dd = Dv[d];

    float4 hv = *(const float4*)&g_h0[(chunk * DI + d) * NST + nq * 4];
    float h0 = hv.x, h1 = hv.y, h2 = hv.z, h3 = hv.w;

    auto issue = [&](int t0, int buf) {
        for (int q = tid; q < 896; q += 256) {
            if (q < 768) {
                int arr = q >> 8;
                int rem = q & 255;
                int tq  = rem >> 4;
                int v   = (rem & 15) * 4;
                int t   = tbase + t0 + tq;
                if      (arr == 0) cp_async16p(&s_delta[buf][tq][v], g_proj + (size_t)t * NPROJ + dbase + v);
                else if (arr == 1) cp_async16p(&s_xi[buf][tq][v],    g_xi   + (size_t)t * DI + dbase + v);
                else               cp_async16p(&s_res[buf][tq][v],   g_xr   + (size_t)t * (2*DI) + DI + dbase + v);
            } else {
                int rem = q - 768;
                int arr = rem >> 6;
                int r2  = rem & 63;
                int tq  = r2 >> 2;
                int v   = (r2 & 3) * 4;
                int t   = tbase + t0 + tq;
                if (arr == 0) cp_async16p(&s_B[buf][tq][v], g_proj + (size_t)t * NPROJ + DI + v);
                else          cp_async16p(&s_C[buf][tq][v], g_proj + (size_t)t * NPROJ + DI + NST + v);
            }
        }
        cp_commit();
    };

    issue(0, 0);
    int buf = 0;
    const int NT2 = CH / TT;
    for (int it = 0; it < NT2; it++) {
        if (it + 1 < NT2) { issue((it + 1) * TT, buf ^ 1); cp_wait<1>(); }
        else              { cp_wait<0>(); }
        __syncthreads();

        int t0 = tbase + it * TT;
#pragma unroll
        for (int tt = 0; tt < TT; tt++) {
            float del = s_delta[buf][tt][dl];
            float xv  = s_xi[buf][tt][dl];
            float4 bv = *(const float4*)&s_B[buf][tt][nq * 4];
            float4 cv = *(const float4*)&s_C[buf][tt][nq * 4];
            float dx = del * xv;
            float e0 = __expf(del * A0), e1 = __expf(del * A1);
            float e2 = __expf(del * A2), e3 = __expf(del * A3);
            h0 = fmaf(e0, h0, dx * bv.x);
            h1 = fmaf(e1, h1, dx * bv.y);
            h2 = fmaf(e2, h2, dx * bv.z);
            h3 = fmaf(e3, h3, dx * bv.w);
            float yv = h0 * cv.x;
            yv = fmaf(h1, cv.y, yv);
            yv = fmaf(h2, cv.z, yv);
            yv = fmaf(h3, cv.w, yv);
            yv += __shfl_xor_sync(0xffffffffu, yv, 1);
            yv += __shfl_xor_sync(0xffffffffu, yv, 2);
            if (nq == 0) {
                float r  = s_res[buf][tt][dl];
                float y  = fmaf(xv, Dd, yv);
                float zv = y * (r / (1.f + __expf(-r)));
                g_ahi[(size_t)(t0 + tt) * DI + d] = __float2half_rn(zv);
            }
        }
        __syncthreads();
        buf ^= 1;
    }
}

// ============================================================================
// launch
// ============================================================================
extern "C" void kernel_launch(void* const* d_in, const int* in_sizes, int n_in,
                              void* d_out, int out_size)
{
    const float* x      = (const float*)d_in[0];
    const float* W_in   = (const float*)d_in[1];
    const float* b_in   = (const float*)d_in[2];
    const float* W_conv = (const float*)d_in[3];
    const float* b_conv = (const float*)d_in[4];
    const float* W_x    = (const float*)d_in[5];
    const float* b_x    = (const float*)d_in[6];
    const float* W_out  = (const float*)d_in[7];
    const float* b_out  = (const float*)d_in[8];
    const float* A_log  = (const float*)d_in[9];
    const float* Dv     = (const float*)d_in[10];
    float* out = (float*)d_out;

    float *xr, *proj;
    __half *ahi, *alo, *win_h, *wx_h, *wout_h;
    cudaGetSymbolAddress((void**)&xr,     g_xr);
    cudaGetSymbolAddress((void**)&proj,   g_proj);
    cudaGetSymbolAddress((void**)&ahi,    g_ahi);
    cudaGetSymbolAddress((void**)&alo,    g_alo);
    cudaGetSymbolAddress((void**)&win_h,  g_win_h);
    cudaGetSymbolAddress((void**)&wx_h,   g_wx_h);
    cudaGetSymbolAddress((void**)&wout_h, g_wout_h);

    static bool attr_done = false;
    if (!attr_done) {
        cudaFuncSetAttribute(gemm_mma<0,1>, cudaFuncAttributeMaxDynamicSharedMemorySize, GEMM_SMEM_NT(1));
        cudaFuncSetAttribute(gemm_mma<1,2>, cudaFuncAttributeMaxDynamicSharedMemorySize, GEMM_SMEM_NT(2));
        attr_done = true;
    }

    cvt_all<<<(N4_TOT + 255) / 256, 256>>>(x, W_in, W_x, W_out);

    {   // GEMM1 (single-term A): xr = x @ W_in.T + b_in
        dim3 grid((2 * DI) / 128, L_SEQ / 128);
        gemm_mma<0,1><<<grid, 256, GEMM_SMEM_NT(1)>>>(ahi, alo, win_h, b_in, xr,
                                                      2 * DI, DM, 2 * DI);
    }
    conv_silu_k<<<(L_SEQ * DI / 4) / 256, 256>>>(W_conv, b_conv);

    {   // GEMM2 (2-term A): proj = xi @ W_x.T + b_x (softplus on delta)
        dim3 grid((NPROJ + 127) / 128, L_SEQ / 128);
        gemm_mma<1,2><<<grid, 256, GEMM_SMEM_NT(2)>>>(ahi, alo, wx_h, b_x, proj,
                                                      NPROJ, DI, NPROJ);
    }
    {   // chunked scan
        dim3 g1(DI / SD, NCH);
        scan_p1<<<g1, 256>>>(A_log);
        scan_comb<<<(DI * NST) / 256, 256>>>();
        scan_p3<<<g1, 256>>>(A_log, Dv);
    }
    {   // GEMM3 (single-term A): out = z @ W_out.T + b_out
        dim3 grid(DM / 128, L_SEQ / 128);
        gemm_mma<0,1><<<grid, 256, GEMM_SMEM_NT(1)>>>(ahi, alo, wout_h, b_out, out,
                                                      DM, DI, DM);
    }
}

// round 10
// speedup vs baseline: 1.4739x; 1.1858x over previous
#include <cuda_runtime.h>
#include <cuda_fp16.h>
#include <math.h>
#include <stdint.h>

// ---------------- problem constants ----------------
#define L_SEQ 2048
#define DM    1024
#define DI    2048
#define NST   16
#define KC    4
#define NPROJ (DI + 2*NST)   // 2080

#define NCH   16
#define CH    128
#define TT    16
#define SD    64

// ---------------- scratch (device globals) ----------------
__device__ float g_xr  [L_SEQ * 2 * DI];
__device__ float g_xi  [L_SEQ * DI];
__device__ float g_proj[L_SEQ * NPROJ];

__device__ __half g_ah    [L_SEQ * DI];      // activation fp16 (single term)
__device__ __half g_win_h [2 * DI * DM];
__device__ __half g_wx_h  [NPROJ * DI];
__device__ __half g_wout_h[DM * DI];

__device__ float g_cA[NCH * DI * NST];
__device__ float g_cB[NCH * DI * NST];
__device__ float g_h0[NCH * DI * NST];

__device__ __forceinline__ float softplus_f(float x) {
    return fmaxf(x, 0.f) + log1pf(expf(-fabsf(x)));
}

#define LOG2E 1.4426950408889634f

// ---------------- PTX helpers ----------------
__device__ __forceinline__ uint32_t smem_u32(const void* p) {
    uint32_t a;
    asm("{ .reg .u64 t; cvta.to.shared.u64 t, %1; cvt.u32.u64 %0, t; }" : "=r"(a) : "l"(p));
    return a;
}
__device__ __forceinline__ void cp_async16(uint32_t sm, const void* gm) {
    asm volatile("cp.async.ca.shared.global [%0], [%1], 16;" :: "r"(sm), "l"(gm));
}
__device__ __forceinline__ void cp_async16p(void* sm, const void* gm) {
    cp_async16(smem_u32(sm), gm);
}
__device__ __forceinline__ void cp_commit() { asm volatile("cp.async.commit_group;"); }
template<int N> __device__ __forceinline__ void cp_wait() {
    asm volatile("cp.async.wait_group %0;" :: "n"(N));
}
__device__ __forceinline__ void ldm_x4(uint32_t* r, uint32_t addr) {
    asm volatile("ldmatrix.sync.aligned.m8n8.x4.shared.b16 {%0,%1,%2,%3}, [%4];"
        : "=r"(r[0]), "=r"(r[1]), "=r"(r[2]), "=r"(r[3]) : "r"(addr));
}
__device__ __forceinline__ void mma_f16(float* d, const uint32_t* a, const uint32_t* b) {
    asm volatile(
        "mma.sync.aligned.m16n8k16.row.col.f32.f16.f16.f32 "
        "{%0,%1,%2,%3}, {%4,%5,%6,%7}, {%8,%9}, {%0,%1,%2,%3};"
        : "+f"(d[0]), "+f"(d[1]), "+f"(d[2]), "+f"(d[3])
        : "r"(a[0]), "r"(a[1]), "r"(a[2]), "r"(a[3]), "r"(b[0]), "r"(b[1]));
}
__device__ __forceinline__ float ex2f(float x) {
    float r;
    asm("ex2.approx.f32 %0, %1;" : "=f"(r) : "f"(x));
    return r;
}

// ============================================================================
// One fused convert kernel: weights -> fp16; x -> fp16.
// ============================================================================
#define N4_X   (L_SEQ * DM / 4)
#define N4_WIN (2 * DI * DM / 4)
#define N4_WX  (NPROJ * DI / 4)
#define N4_WO  (DM * DI / 4)
#define N4_TOT (N4_X + N4_WIN + N4_WX + N4_WO)

__global__ __launch_bounds__(256)
void cvt_all(const float* __restrict__ x, const float* __restrict__ W_in,
             const float* __restrict__ W_x, const float* __restrict__ W_out)
{
    int i = blockIdx.x * blockDim.x + threadIdx.x;
    if (i >= N4_TOT) return;

    const float* src; __half* dst; int j;
    if (i < N4_X)                       { j = i;                         src = x;     dst = g_ah; }
    else if (i < N4_X + N4_WIN)         { j = i - N4_X;                  src = W_in;  dst = g_win_h; }
    else if (i < N4_X + N4_WIN + N4_WX) { j = i - N4_X - N4_WIN;         src = W_x;   dst = g_wx_h; }
    else                                { j = i - N4_X - N4_WIN - N4_WX; src = W_out; dst = g_wout_h; }
    float4 v = ((const float4*)src)[j];
    ((__half2*)dst)[j*2+0] = __half2(__float2half_rn(v.x), __float2half_rn(v.y));
    ((__half2*)dst)[j*2+1] = __half2(__float2half_rn(v.z), __float2half_rn(v.w));
}

// ============================================================================
// fp16 GEMM via mma.sync m16n8k16 (single-term A).
// Block 128x128, BK=64, 8 warps (4M x 2N). 2-stage ring, 1 barrier/stage.
// ============================================================================
#define ROWB  144
#define MATB  (128 * ROWB)
#define GEMM_SMEM (2 * 2 * MATB)   // 73728

__device__ __forceinline__ void gemm_load_stage(
    uint32_t sb, int buf, int k0,
    const __half* __restrict__ Ah, const __half* __restrict__ Wh,
    int m0, int n0, int Nc, int Kd, int tid)
{
    uint32_t base = sb + buf * (2 * MATB);
#pragma unroll
    for (int it = 0; it < 8; it++) {
        int q   = tid + it * 256;
        int mat = q >> 10;         // 0:A 1:W
        int rem = q & 1023;
        int row = rem >> 3;
        int ch  = rem & 7;
        uint32_t dst = base + mat * MATB + row * ROWB + ch * 16;
        const __half* src;
        if (mat == 0) {
            src = Ah + (size_t)(m0 + row) * Kd + k0 + ch * 8;
        } else {
            int wr = n0 + row; if (wr >= Nc) wr = Nc - 1;
            src = Wh + (size_t)wr * Kd + k0 + ch * 8;
        }
        cp_async16(dst, src);
    }
    cp_commit();
}

template<int ACT>
__global__ __launch_bounds__(256, 2)
void gemm_mma(const __half* __restrict__ Ah, const __half* __restrict__ Wh,
              const float* __restrict__ bias, float* __restrict__ C,
              int Nc, int Kd, int ldc)
{
    extern __shared__ char smraw[];
    uint32_t sb = smem_u32(smraw);

    int tid  = threadIdx.x;
    int wid  = tid >> 5;
    int lane = tid & 31;
    int wm   = wid & 3;
    int wn   = wid >> 2;
    int m0 = blockIdx.y * 128;
    int n0 = blockIdx.x * 128;

    float acc[2][8][4];
#pragma unroll
    for (int i = 0; i < 2; i++)
#pragma unroll
        for (int j = 0; j < 8; j++)
#pragma unroll
            for (int k = 0; k < 4; k++) acc[i][j][k] = 0.f;

    int aRow = wm * 32 + (lane & 15);
    int aColHalf = (lane >> 4) << 3;
    int bRow = wn * 64 + ((lane >> 4) & 1) * 8 + (lane & 7);
    int bColHalf = ((lane >> 3) & 1) << 3;

    const int NSTAGE = Kd / 64;
    gemm_load_stage(sb, 0, 0, Ah, Wh, m0, n0, Nc, Kd, tid);

    int buf = 0;
    for (int s = 0; s < NSTAGE; s++) {
        cp_wait<0>();
        __syncthreads();
        if (s + 1 < NSTAGE)
            gemm_load_stage(sb, buf ^ 1, (s + 1) * 64, Ah, Wh, m0, n0, Nc, Kd, tid);

        uint32_t bA = sb + buf * (2 * MATB);
        uint32_t bW = bA + MATB;
#pragma unroll
        for (int kc = 0; kc < 4; kc++) {
            int acol2 = (kc * 16 + aColHalf) * 2;
            int bcol2 = (kc * 16 + bColHalf) * 2;
            uint32_t ah[2][4], bh[4][4];
#pragma unroll
            for (int mt = 0; mt < 2; mt++) {
                uint32_t off = (uint32_t)((aRow + mt * 16) * ROWB + acol2);
                ldm_x4(ah[mt], bA + off);
            }
#pragma unroll
            for (int ntp = 0; ntp < 4; ntp++) {
                uint32_t off = (uint32_t)((bRow + ntp * 16) * ROWB + bcol2);
                ldm_x4(bh[ntp], bW + off);
            }
#pragma unroll
            for (int ntp = 0; ntp < 4; ntp++) {
#pragma unroll
                for (int mt = 0; mt < 2; mt++) {
                    mma_f16(acc[mt][2*ntp+0], ah[mt], bh[ntp] + 0);
                    mma_f16(acc[mt][2*ntp+1], ah[mt], bh[ntp] + 2);
                }
            }
        }
        buf ^= 1;
    }

#pragma unroll
    for (int mt = 0; mt < 2; mt++) {
        int r0 = m0 + wm * 32 + mt * 16 + (lane >> 2);
#pragma unroll
        for (int nt = 0; nt < 8; nt++) {
            int c = n0 + wn * 64 + nt * 8 + 2 * (lane & 3);
            if (c < Nc) {
                float b0 = bias[c], b1 = bias[c + 1];
                float v0 = acc[mt][nt][0] + b0;
                float v1 = acc[mt][nt][1] + b1;
                float v2 = acc[mt][nt][2] + b0;
                float v3 = acc[mt][nt][3] + b1;
                if (ACT == 1) {
                    if (c     < DI) { v0 = softplus_f(v0); v2 = softplus_f(v2); }
                    if (c + 1 < DI) { v1 = softplus_f(v1); v3 = softplus_f(v3); }
                }
                *(float2*)&C[(size_t)r0 * ldc + c]       = make_float2(v0, v1);
                *(float2*)&C[(size_t)(r0 + 8) * ldc + c] = make_float2(v2, v3);
            }
        }
    }
}

// ============================================================================
// Depthwise causal conv (K=4) + silu, 4 channels/thread.
// Writes fp32 xi AND fp16 (GEMM2's A, single term).
// ============================================================================
__global__ __launch_bounds__(256)
void conv_silu_k(const float* __restrict__ Wc, const float* __restrict__ bc)
{
    int idx = blockIdx.x * blockDim.x + threadIdx.x;
    int t  = idx >> 9;
    int d4 = (idx & 511) << 2;

    float4 acc = *(const float4*)&bc[d4];
#pragma unroll
    for (int k = 0; k < KC; k++) {
        int tt = t - (KC - 1) + k;
        if (tt >= 0) {
            float4 v = *(const float4*)&g_xr[(size_t)tt * (2 * DI) + d4];
            acc.x = fmaf(Wc[(d4 + 0) * KC + k], v.x, acc.x);
            acc.y = fmaf(Wc[(d4 + 1) * KC + k], v.y, acc.y);
            acc.z = fmaf(Wc[(d4 + 2) * KC + k], v.z, acc.z);
            acc.w = fmaf(Wc[(d4 + 3) * KC + k], v.w, acc.w);
        }
    }
    float s0 = acc.x / (1.f + __expf(-acc.x));
    float s1 = acc.y / (1.f + __expf(-acc.y));
    float s2 = acc.z / (1.f + __expf(-acc.z));
    float s3 = acc.w / (1.f + __expf(-acc.w));
    size_t o = (size_t)t * DI + d4;
    *(float4*)&g_xi[o] = make_float4(s0, s1, s2, s3);
    *(__half2*)&g_ah[o]     = __half2(__float2half_rn(s0), __float2half_rn(s1));
    *(__half2*)&g_ah[o + 2] = __half2(__float2half_rn(s2), __float2half_rn(s3));
}

// ============================================================================
// Chunked selective scan; exp via ex2 with log2e pre-folded into A.
// ============================================================================
__global__ __launch_bounds__(256, 1)
void scan_p1(const float* __restrict__ A_log)
{
    __shared__ float s_delta[2][TT][SD];
    __shared__ float s_xi   [2][TT][SD];
    __shared__ float s_B    [2][TT][NST];

    int tid = threadIdx.x;
    int nq = tid & 3;
    int dl = tid >> 2;
    int dbase = blockIdx.x * SD;
    int d = dbase + dl;
    int chunk = blockIdx.y;
    int tbase = chunk * CH;

    float4 alv = *(const float4*)&A_log[d * NST + nq * 4];
    float A0 = -__expf(alv.x) * LOG2E, A1 = -__expf(alv.y) * LOG2E;
    float A2 = -__expf(alv.z) * LOG2E, A3 = -__expf(alv.w) * LOG2E;

    float ap0 = 1.f, ap1 = 1.f, ap2 = 1.f, ap3 = 1.f;
    float h0 = 0.f, h1 = 0.f, h2 = 0.f, h3 = 0.f;

    auto issue = [&](int t0, int buf) {
        for (int q = tid; q < 576; q += 256) {
            if (q < 512) {
                int arr = q >> 8;
                int rem = q & 255;
                int tq  = rem >> 4;
                int v   = (rem & 15) * 4;
                int t   = tbase + t0 + tq;
                if (arr == 0)
                    cp_async16p(&s_delta[buf][tq][v], g_proj + (size_t)t * NPROJ + dbase + v);
                else
                    cp_async16p(&s_xi[buf][tq][v], g_xi + (size_t)t * DI + dbase + v);
            } else {
                int rem = q - 512;
                int tq  = rem >> 2;
                int v   = (rem & 3) * 4;
                int t   = tbase + t0 + tq;
                cp_async16p(&s_B[buf][tq][v], g_proj + (size_t)t * NPROJ + DI + v);
            }
        }
        cp_commit();
    };

    issue(0, 0);
    int buf = 0;
    const int NT2 = CH / TT;
    for (int it = 0; it < NT2; it++) {
        if (it + 1 < NT2) { issue((it + 1) * TT, buf ^ 1); cp_wait<1>(); }
        else              { cp_wait<0>(); }
        __syncthreads();
#pragma unroll
        for (int tt = 0; tt < TT; tt++) {
            float del = s_delta[buf][tt][dl];
            float xv  = s_xi[buf][tt][dl];
            float4 bv = *(const float4*)&s_B[buf][tt][nq * 4];
            float dx = del * xv;
            float e0 = ex2f(del * A0), e1 = ex2f(del * A1);
            float e2 = ex2f(del * A2), e3 = ex2f(del * A3);
            ap0 *= e0; ap1 *= e1; ap2 *= e2; ap3 *= e3;
            h0 = fmaf(e0, h0, dx * bv.x);
            h1 = fmaf(e1, h1, dx * bv.y);
            h2 = fmaf(e2, h2, dx * bv.z);
            h3 = fmaf(e3, h3, dx * bv.w);
        }
        __syncthreads();
        buf ^= 1;
    }
    int idx = (chunk * DI + d) * NST + nq * 4;
    *(float4*)&g_cA[idx] = make_float4(ap0, ap1, ap2, ap3);
    *(float4*)&g_cB[idx] = make_float4(h0, h1, h2, h3);
}

__global__ __launch_bounds__(256)
void scan_comb()
{
    int dn = blockIdx.x * blockDim.x + threadIdx.x;
    float h = 0.f;
#pragma unroll
    for (int c = 0; c < NCH; c++) {
        int idx = c * (DI * NST) + dn;
        g_h0[idx] = h;
        h = fmaf(g_cA[idx], h, g_cB[idx]);
    }
}

__global__ __launch_bounds__(256, 1)
void scan_p3(const float* __restrict__ A_log, const float* __restrict__ Dv)
{
    __shared__ float s_delta[2][TT][SD];
    __shared__ float s_xi   [2][TT][SD];
    __shared__ float s_res  [2][TT][SD];
    __shared__ float s_B    [2][TT][NST];
    __shared__ float s_C    [2][TT][NST];

    int tid = threadIdx.x;
    int nq = tid & 3;
    int dl = tid >> 2;
    int dbase = blockIdx.x * SD;
    int d = dbase + dl;
    int chunk = blockIdx.y;
    int tbase = chunk * CH;

    float4 alv = *(const float4*)&A_log[d * NST + nq * 4];
    float A0 = -__expf(alv.x) * LOG2E, A1 = -__expf(alv.y) * LOG2E;
    float A2 = -__expf(alv.z) * LOG2E, A3 = -__expf(alv.w) * LOG2E;
    float Dd = Dv[d];

    float4 hv = *(const float4*)&g_h0[(chunk * DI + d) * NST + nq * 4];
    float h0 = hv.x, h1 = hv.y, h2 = hv.z, h3 = hv.w;

    auto issue = [&](int t0, int buf) {
        for (int q = tid; q < 896; q += 256) {
            if (q < 768) {
                int arr = q >> 8;
                int rem = q & 255;
                int tq  = rem >> 4;
                int v   = (rem & 15) * 4;
                int t   = tbase + t0 + tq;
                if      (arr == 0) cp_async16p(&s_delta[buf][tq][v], g_proj + (size_t)t * NPROJ + dbase + v);
                else if (arr == 1) cp_async16p(&s_xi[buf][tq][v],    g_xi   + (size_t)t * DI + dbase + v);
                else               cp_async16p(&s_res[buf][tq][v],   g_xr   + (size_t)t * (2*DI) + DI + dbase + v);
            } else {
                int rem = q - 768;
                int arr = rem >> 6;
                int r2  = rem & 63;
                int tq  = r2 >> 2;
                int v   = (r2 & 3) * 4;
                int t   = tbase + t0 + tq;
                if (arr == 0) cp_async16p(&s_B[buf][tq][v], g_proj + (size_t)t * NPROJ + DI + v);
                else          cp_async16p(&s_C[buf][tq][v], g_proj + (size_t)t * NPROJ + DI + NST + v);
            }
        }
        cp_commit();
    };

    issue(0, 0);
    int buf = 0;
    const int NT2 = CH / TT;
    for (int it = 0; it < NT2; it++) {
        if (it + 1 < NT2) { issue((it + 1) * TT, buf ^ 1); cp_wait<1>(); }
        else              { cp_wait<0>(); }
        __syncthreads();

        int t0 = tbase + it * TT;
#pragma unroll
        for (int tt = 0; tt < TT; tt++) {
            float del = s_delta[buf][tt][dl];
            float xv  = s_xi[buf][tt][dl];
            float4 bv = *(const float4*)&s_B[buf][tt][nq * 4];
            float4 cv = *(const float4*)&s_C[buf][tt][nq * 4];
            float dx = del * xv;
            float e0 = ex2f(del * A0), e1 = ex2f(del * A1);
            float e2 = ex2f(del * A2), e3 = ex2f(del * A3);
            h0 = fmaf(e0, h0, dx * bv.x);
            h1 = fmaf(e1, h1, dx * bv.y);
            h2 = fmaf(e2, h2, dx * bv.z);
            h3 = fmaf(e3, h3, dx * bv.w);
            float yv = h0 * cv.x;
            yv = fmaf(h1, cv.y, yv);
            yv = fmaf(h2, cv.z, yv);
            yv = fmaf(h3, cv.w, yv);
            yv += __shfl_xor_sync(0xffffffffu, yv, 1);
            yv += __shfl_xor_sync(0xffffffffu, yv, 2);
            if (nq == 0) {
                float r  = s_res[buf][tt][dl];
                float y  = fmaf(xv, Dd, yv);
                float zv = y * (r / (1.f + __expf(-r)));
                g_ah[(size_t)(t0 + tt) * DI + d] = __float2half_rn(zv);
            }
        }
        __syncthreads();
        buf ^= 1;
    }
}

// ============================================================================
// launch
// ============================================================================
extern "C" void kernel_launch(void* const* d_in, const int* in_sizes, int n_in,
                              void* d_out, int out_size)
{
    const float* x      = (const float*)d_in[0];
    const float* W_in   = (const float*)d_in[1];
    const float* b_in   = (const float*)d_in[2];
    const float* W_conv = (const float*)d_in[3];
    const float* b_conv = (const float*)d_in[4];
    const float* W_x    = (const float*)d_in[5];
    const float* b_x    = (const float*)d_in[6];
    const float* W_out  = (const float*)d_in[7];
    const float* b_out  = (const float*)d_in[8];
    const float* A_log  = (const float*)d_in[9];
    const float* Dv     = (const float*)d_in[10];
    float* out = (float*)d_out;

    float *xr, *proj;
    __half *ah, *win_h, *wx_h, *wout_h;
    cudaGetSymbolAddress((void**)&xr,     g_xr);
    cudaGetSymbolAddress((void**)&proj,   g_proj);
    cudaGetSymbolAddress((void**)&ah,     g_ah);
    cudaGetSymbolAddress((void**)&win_h,  g_win_h);
    cudaGetSymbolAddress((void**)&wx_h,   g_wx_h);
    cudaGetSymbolAddress((void**)&wout_h, g_wout_h);

    static bool attr_done = false;
    if (!attr_done) {
        cudaFuncSetAttribute(gemm_mma<0>, cudaFuncAttributeMaxDynamicSharedMemorySize, GEMM_SMEM);
        cudaFuncSetAttribute(gemm_mma<1>, cudaFuncAttributeMaxDynamicSharedMemorySize, GEMM_SMEM);
        attr_done = true;
    }

    cvt_all<<<(N4_TOT + 255) / 256, 256>>>(x, W_in, W_x, W_out);

    {   // GEMM1: xr = x @ W_in.T + b_in
        dim3 grid((2 * DI) / 128, L_SEQ / 128);
        gemm_mma<0><<<grid, 256, GEMM_SMEM>>>(ah, win_h, b_in, xr,
                                              2 * DI, DM, 2 * DI);
    }
    conv_silu_k<<<(L_SEQ * DI / 4) / 256, 256>>>(W_conv, b_conv);

    {   // GEMM2: proj = xi @ W_x.T + b_x (softplus on delta)
        dim3 grid((NPROJ + 127) / 128, L_SEQ / 128);
        gemm_mma<1><<<grid, 256, GEMM_SMEM>>>(ah, wx_h, b_x, proj,
                                              NPROJ, DI, NPROJ);
    }
    {   // chunked scan
        dim3 g1(DI / SD, NCH);
        scan_p1<<<g1, 256>>>(A_log);
        scan_comb<<<(DI * NST) / 256, 256>>>();
        scan_p3<<<g1, 256>>>(A_log, Dv);
    }
    {   // GEMM3: out = z @ W_out.T + b_out
        dim3 grid(DM / 128, L_SEQ / 128);
        gemm_mma<0><<<grid, 256, GEMM_SMEM>>>(ah, wout_h, b_out, out,
                                              DM, DI, DM);
    }
}

// round 11
// speedup vs baseline: 1.5261x; 1.0354x over previous
#include <cuda_runtime.h>
#include <cuda_fp16.h>
#include <math.h>
#include <stdint.h>

// ---------------- problem constants ----------------
#define L_SEQ 2048
#define DM    1024
#define DI    2048
#define NST   16
#define KC    4
#define NPROJ (DI + 2*NST)   // 2080

#define NCH   16
#define CH    128
#define TT    32             // scan time tile (was 16)
#define SD    64

// ---------------- scratch (device globals) ----------------
__device__ float g_xr  [L_SEQ * 2 * DI];
__device__ float g_xi  [L_SEQ * DI];
__device__ float g_proj[L_SEQ * NPROJ];

__device__ __half g_ah    [L_SEQ * DI];
__device__ __half g_win_h [2 * DI * DM];
__device__ __half g_wx_h  [NPROJ * DI];
__device__ __half g_wout_h[DM * DI];

__device__ float g_cA[NCH * DI * NST];
__device__ float g_cB[NCH * DI * NST];
__device__ float g_h0[NCH * DI * NST];

__device__ __forceinline__ float softplus_f(float x) {
    return fmaxf(x, 0.f) + log1pf(expf(-fabsf(x)));
}

#define LOG2E 1.4426950408889634f

// ---------------- PTX helpers ----------------
__device__ __forceinline__ uint32_t smem_u32(const void* p) {
    uint32_t a;
    asm("{ .reg .u64 t; cvta.to.shared.u64 t, %1; cvt.u32.u64 %0, t; }" : "=r"(a) : "l"(p));
    return a;
}
__device__ __forceinline__ void cp_async16(uint32_t sm, const void* gm) {
    asm volatile("cp.async.ca.shared.global [%0], [%1], 16;" :: "r"(sm), "l"(gm));
}
__device__ __forceinline__ void cp_async16p(void* sm, const void* gm) {
    cp_async16(smem_u32(sm), gm);
}
__device__ __forceinline__ void cp_commit() { asm volatile("cp.async.commit_group;"); }
template<int N> __device__ __forceinline__ void cp_wait() {
    asm volatile("cp.async.wait_group %0;" :: "n"(N));
}
__device__ __forceinline__ void ldm_x4(uint32_t* r, uint32_t addr) {
    asm volatile("ldmatrix.sync.aligned.m8n8.x4.shared.b16 {%0,%1,%2,%3}, [%4];"
        : "=r"(r[0]), "=r"(r[1]), "=r"(r[2]), "=r"(r[3]) : "r"(addr));
}
__device__ __forceinline__ void mma_f16(float* d, const uint32_t* a, const uint32_t* b) {
    asm volatile(
        "mma.sync.aligned.m16n8k16.row.col.f32.f16.f16.f32 "
        "{%0,%1,%2,%3}, {%4,%5,%6,%7}, {%8,%9}, {%0,%1,%2,%3};"
        : "+f"(d[0]), "+f"(d[1]), "+f"(d[2]), "+f"(d[3])
        : "r"(a[0]), "r"(a[1]), "r"(a[2]), "r"(a[3]), "r"(b[0]), "r"(b[1]));
}
__device__ __forceinline__ float ex2f(float x) {
    float r;
    asm("ex2.approx.f32 %0, %1;" : "=f"(r) : "f"(x));
    return r;
}

// ============================================================================
// One fused convert kernel: weights -> fp16; x -> fp16.
// ============================================================================
#define N4_X   (L_SEQ * DM / 4)
#define N4_WIN (2 * DI * DM / 4)
#define N4_WX  (NPROJ * DI / 4)
#define N4_WO  (DM * DI / 4)
#define N4_TOT (N4_X + N4_WIN + N4_WX + N4_WO)

__global__ __launch_bounds__(256)
void cvt_all(const float* __restrict__ x, const float* __restrict__ W_in,
             const float* __restrict__ W_x, const float* __restrict__ W_out)
{
    int i = blockIdx.x * blockDim.x + threadIdx.x;
    if (i >= N4_TOT) return;

    const float* src; __half* dst; int j;
    if (i < N4_X)                       { j = i;                         src = x;     dst = g_ah; }
    else if (i < N4_X + N4_WIN)         { j = i - N4_X;                  src = W_in;  dst = g_win_h; }
    else if (i < N4_X + N4_WIN + N4_WX) { j = i - N4_X - N4_WIN;         src = W_x;   dst = g_wx_h; }
    else                                { j = i - N4_X - N4_WIN - N4_WX; src = W_out; dst = g_wout_h; }
    float4 v = ((const float4*)src)[j];
    ((__half2*)dst)[j*2+0] = __half2(__float2half_rn(v.x), __float2half_rn(v.y));
    ((__half2*)dst)[j*2+1] = __half2(__float2half_rn(v.z), __float2half_rn(v.w));
}

// ============================================================================
// fp16 GEMM via mma.sync m16n8k16 (single-term A) — unchanged from R10
// (measured at the mma.sync ceiling, ~296 TF/s).
// ============================================================================
#define ROWB  144
#define MATB  (128 * ROWB)
#define GEMM_SMEM (2 * 2 * MATB)   // 73728

__device__ __forceinline__ void gemm_load_stage(
    uint32_t sb, int buf, int k0,
    const __half* __restrict__ Ah, const __half* __restrict__ Wh,
    int m0, int n0, int Nc, int Kd, int tid)
{
    uint32_t base = sb + buf * (2 * MATB);
#pragma unroll
    for (int it = 0; it < 8; it++) {
        int q   = tid + it * 256;
        int mat = q >> 10;
        int rem = q & 1023;
        int row = rem >> 3;
        int ch  = rem & 7;
        uint32_t dst = base + mat * MATB + row * ROWB + ch * 16;
        const __half* src;
        if (mat == 0) {
            src = Ah + (size_t)(m0 + row) * Kd + k0 + ch * 8;
        } else {
            int wr = n0 + row; if (wr >= Nc) wr = Nc - 1;
            src = Wh + (size_t)wr * Kd + k0 + ch * 8;
        }
        cp_async16(dst, src);
    }
    cp_commit();
}

template<int ACT>
__global__ __launch_bounds__(256, 2)
void gemm_mma(const __half* __restrict__ Ah, const __half* __restrict__ Wh,
              const float* __restrict__ bias, float* __restrict__ C,
              int Nc, int Kd, int ldc)
{
    extern __shared__ char smraw[];
    uint32_t sb = smem_u32(smraw);

    int tid  = threadIdx.x;
    int wid  = tid >> 5;
    int lane = tid & 31;
    int wm   = wid & 3;
    int wn   = wid >> 2;
    int m0 = blockIdx.y * 128;
    int n0 = blockIdx.x * 128;

    float acc[2][8][4];
#pragma unroll
    for (int i = 0; i < 2; i++)
#pragma unroll
        for (int j = 0; j < 8; j++)
#pragma unroll
            for (int k = 0; k < 4; k++) acc[i][j][k] = 0.f;

    int aRow = wm * 32 + (lane & 15);
    int aColHalf = (lane >> 4) << 3;
    int bRow = wn * 64 + ((lane >> 4) & 1) * 8 + (lane & 7);
    int bColHalf = ((lane >> 3) & 1) << 3;

    const int NSTAGE = Kd / 64;
    gemm_load_stage(sb, 0, 0, Ah, Wh, m0, n0, Nc, Kd, tid);

    int buf = 0;
    for (int s = 0; s < NSTAGE; s++) {
        cp_wait<0>();
        __syncthreads();
        if (s + 1 < NSTAGE)
            gemm_load_stage(sb, buf ^ 1, (s + 1) * 64, Ah, Wh, m0, n0, Nc, Kd, tid);

        uint32_t bA = sb + buf * (2 * MATB);
        uint32_t bW = bA + MATB;
#pragma unroll
        for (int kc = 0; kc < 4; kc++) {
            int acol2 = (kc * 16 + aColHalf) * 2;
            int bcol2 = (kc * 16 + bColHalf) * 2;
            uint32_t ah[2][4], bh[4][4];
#pragma unroll
            for (int mt = 0; mt < 2; mt++) {
                uint32_t off = (uint32_t)((aRow + mt * 16) * ROWB + acol2);
                ldm_x4(ah[mt], bA + off);
            }
#pragma unroll
            for (int ntp = 0; ntp < 4; ntp++) {
                uint32_t off = (uint32_t)((bRow + ntp * 16) * ROWB + bcol2);
                ldm_x4(bh[ntp], bW + off);
            }
#pragma unroll
            for (int ntp = 0; ntp < 4; ntp++) {
#pragma unroll
                for (int mt = 0; mt < 2; mt++) {
                    mma_f16(acc[mt][2*ntp+0], ah[mt], bh[ntp] + 0);
                    mma_f16(acc[mt][2*ntp+1], ah[mt], bh[ntp] + 2);
                }
            }
        }
        buf ^= 1;
    }

#pragma unroll
    for (int mt = 0; mt < 2; mt++) {
        int r0 = m0 + wm * 32 + mt * 16 + (lane >> 2);
#pragma unroll
        for (int nt = 0; nt < 8; nt++) {
            int c = n0 + wn * 64 + nt * 8 + 2 * (lane & 3);
            if (c < Nc) {
                float b0 = bias[c], b1 = bias[c + 1];
                float v0 = acc[mt][nt][0] + b0;
                float v1 = acc[mt][nt][1] + b1;
                float v2 = acc[mt][nt][2] + b0;
                float v3 = acc[mt][nt][3] + b1;
                if (ACT == 1) {
                    if (c     < DI) { v0 = softplus_f(v0); v2 = softplus_f(v2); }
                    if (c + 1 < DI) { v1 = softplus_f(v1); v3 = softplus_f(v3); }
                }
                *(float2*)&C[(size_t)r0 * ldc + c]       = make_float2(v0, v1);
                *(float2*)&C[(size_t)(r0 + 8) * ldc + c] = make_float2(v2, v3);
            }
        }
    }
}

// ============================================================================
// Depthwise causal conv (K=4) + silu, 4 channels/thread.
// ============================================================================
__global__ __launch_bounds__(256)
void conv_silu_k(const float* __restrict__ Wc, const float* __restrict__ bc)
{
    int idx = blockIdx.x * blockDim.x + threadIdx.x;
    int t  = idx >> 9;
    int d4 = (idx & 511) << 2;

    float4 acc = *(const float4*)&bc[d4];
#pragma unroll
    for (int k = 0; k < KC; k++) {
        int tt = t - (KC - 1) + k;
        if (tt >= 0) {
            float4 v = *(const float4*)&g_xr[(size_t)tt * (2 * DI) + d4];
            acc.x = fmaf(Wc[(d4 + 0) * KC + k], v.x, acc.x);
            acc.y = fmaf(Wc[(d4 + 1) * KC + k], v.y, acc.y);
            acc.z = fmaf(Wc[(d4 + 2) * KC + k], v.z, acc.z);
            acc.w = fmaf(Wc[(d4 + 3) * KC + k], v.w, acc.w);
        }
    }
    float s0 = acc.x / (1.f + __expf(-acc.x));
    float s1 = acc.y / (1.f + __expf(-acc.y));
    float s2 = acc.z / (1.f + __expf(-acc.z));
    float s3 = acc.w / (1.f + __expf(-acc.w));
    size_t o = (size_t)t * DI + d4;
    *(float4*)&g_xi[o] = make_float4(s0, s1, s2, s3);
    *(__half2*)&g_ah[o]     = __half2(__float2half_rn(s0), __float2half_rn(s1));
    *(__half2*)&g_ah[o + 2] = __half2(__float2half_rn(s2), __float2half_rn(s3));
}

// ============================================================================
// Chunked selective scan.  TT=32 tiles; p1 uses the S-trick:
//   prod_t exp2(A'·del_t) = exp2(A' · sum_t del_t)  -> 1 FADD/t instead of 4 FMUL/t
// ============================================================================
__global__ __launch_bounds__(256, 1)
void scan_p1(const float* __restrict__ A_log)
{
    __shared__ float s_delta[2][TT][SD];   // 16 KB
    __shared__ float s_xi   [2][TT][SD];   // 16 KB
    __shared__ float s_B    [2][TT][NST];  //  4 KB

    int tid = threadIdx.x;
    int nq = tid & 3;
    int dl = tid >> 2;
    int dbase = blockIdx.x * SD;
    int d = dbase + dl;
    int chunk = blockIdx.y;
    int tbase = chunk * CH;

    float4 alv = *(const float4*)&A_log[d * NST + nq * 4];
    float A0 = -__expf(alv.x) * LOG2E, A1 = -__expf(alv.y) * LOG2E;
    float A2 = -__expf(alv.z) * LOG2E, A3 = -__expf(alv.w) * LOG2E;

    float S = 0.f;                                   // sum of delta over chunk
    float h0 = 0.f, h1 = 0.f, h2 = 0.f, h3 = 0.f;

    auto issue = [&](int t0, int buf) {
        for (int q = tid; q < 1152; q += 256) {      // 512 delta + 512 xi + 128 B
            if (q < 1024) {
                int arr = q >> 9;
                int rem = q & 511;
                int tq  = rem >> 4;
                int v   = (rem & 15) * 4;
                int t   = tbase + t0 + tq;
                if (arr == 0)
                    cp_async16p(&s_delta[buf][tq][v], g_proj + (size_t)t * NPROJ + dbase + v);
                else
                    cp_async16p(&s_xi[buf][tq][v], g_xi + (size_t)t * DI + dbase + v);
            } else {
                int rem = q - 1024;
                int tq  = rem >> 2;
                int v   = (rem & 3) * 4;
                int t   = tbase + t0 + tq;
                cp_async16p(&s_B[buf][tq][v], g_proj + (size_t)t * NPROJ + DI + v);
            }
        }
        cp_commit();
    };

    issue(0, 0);
    int buf = 0;
    const int NT2 = CH / TT;   // 4
    for (int it = 0; it < NT2; it++) {
        if (it + 1 < NT2) { issue((it + 1) * TT, buf ^ 1); cp_wait<1>(); }
        else              { cp_wait<0>(); }
        __syncthreads();
#pragma unroll
        for (int tt = 0; tt < TT; tt++) {
            float del = s_delta[buf][tt][dl];
            float xv  = s_xi[buf][tt][dl];
            float4 bv = *(const float4*)&s_B[buf][tt][nq * 4];
            float dx = del * xv;
            float e0 = ex2f(del * A0), e1 = ex2f(del * A1);
            float e2 = ex2f(del * A2), e3 = ex2f(del * A3);
            S += del;
            h0 = fmaf(e0, h0, dx * bv.x);
            h1 = fmaf(e1, h1, dx * bv.y);
            h2 = fmaf(e2, h2, dx * bv.z);
            h3 = fmaf(e3, h3, dx * bv.w);
        }
        __syncthreads();
        buf ^= 1;
    }
    int idx = (chunk * DI + d) * NST + nq * 4;
    *(float4*)&g_cA[idx] = make_float4(ex2f(A0 * S), ex2f(A1 * S),
                                       ex2f(A2 * S), ex2f(A3 * S));
    *(float4*)&g_cB[idx] = make_float4(h0, h1, h2, h3);
}

__global__ __launch_bounds__(256)
void scan_comb()
{
    int dn4 = (blockIdx.x * blockDim.x + threadIdx.x) * 4;   // float4 over (d,n)
    float4 h = make_float4(0.f, 0.f, 0.f, 0.f);
#pragma unroll
    for (int c = 0; c < NCH; c++) {
        int idx = c * (DI * NST) + dn4;
        *(float4*)&g_h0[idx] = h;
        float4 a = *(const float4*)&g_cA[idx];
        float4 b = *(const float4*)&g_cB[idx];
        h.x = fmaf(a.x, h.x, b.x);
        h.y = fmaf(a.y, h.y, b.y);
        h.z = fmaf(a.z, h.z, b.z);
        h.w = fmaf(a.w, h.w, b.w);
    }
}

// p3 uses dynamic smem (57.3 KB > 48 KB static limit at TT=32)
#define P3_SMEM (14336 * 4)   // floats: 3*4096 + 2*1024

__global__ __launch_bounds__(256, 1)
void scan_p3(const float* __restrict__ A_log, const float* __restrict__ Dv)
{
    extern __shared__ float sm[];
    float* s_delta = sm;            // [2][TT][SD] = 4096 floats
    float* s_xi    = sm + 4096;
    float* s_res   = sm + 8192;
    float* s_B     = sm + 12288;    // [2][TT][NST] = 1024 floats
    float* s_C     = sm + 13312;

    int tid = threadIdx.x;
    int nq = tid & 3;
    int dl = tid >> 2;
    int dbase = blockIdx.x * SD;
    int d = dbase + dl;
    int chunk = blockIdx.y;
    int tbase = chunk * CH;

    float4 alv = *(const float4*)&A_log[d * NST + nq * 4];
    float A0 = -__expf(alv.x) * LOG2E, A1 = -__expf(alv.y) * LOG2E;
    float A2 = -__expf(alv.z) * LOG2E, A3 = -__expf(alv.w) * LOG2E;
    float Dd = Dv[d];

    float4 hv = *(const float4*)&g_h0[(chunk * DI + d) * NST + nq * 4];
    float h0 = hv.x, h1 = hv.y, h2 = hv.z, h3 = hv.w;

    auto issue = [&](int t0, int buf) {
        for (int q = tid; q < 1792; q += 256) {   // 512*3 big + 128*2 small
            if (q < 1536) {
                int arr = q >> 9;                 // 0 delta, 1 xi, 2 res
                int rem = q & 511;
                int tq  = rem >> 4;
                int v   = (rem & 15) * 4;
                int t   = tbase + t0 + tq;
                int so  = buf * 2048 + tq * SD + v;
                if      (arr == 0) cp_async16p(&s_delta[so], g_proj + (size_t)t * NPROJ + dbase + v);
                else if (arr == 1) cp_async16p(&s_xi[so],    g_xi   + (size_t)t * DI + dbase + v);
                else               cp_async16p(&s_res[so],   g_xr   + (size_t)t * (2*DI) + DI + dbase + v);
            } else {
                int rem = q - 1536;               // 0..255 : B then C
                int arr = rem >> 7;
                int r2  = rem & 127;
                int tq  = r2 >> 2;
                int v   = (r2 & 3) * 4;
                int t   = tbase + t0 + tq;
                int so  = buf * 512 + tq * NST + v;
                if (arr == 0) cp_async16p(&s_B[so], g_proj + (size_t)t * NPROJ + DI + v);
                else          cp_async16p(&s_C[so], g_proj + (size_t)t * NPROJ + DI + NST + v);
            }
        }
        cp_commit();
    };

    issue(0, 0);
    int buf = 0;
    const int NT2 = CH / TT;   // 4
    for (int it = 0; it < NT2; it++) {
        if (it + 1 < NT2) { issue((it + 1) * TT, buf ^ 1); cp_wait<1>(); }
        else              { cp_wait<0>(); }
        __syncthreads();

        int t0 = tbase + it * TT;
#pragma unroll
        for (int tt = 0; tt < TT; tt++) {
            float del = s_delta[buf * 2048 + tt * SD + dl];
            float xv  = s_xi   [buf * 2048 + tt * SD + dl];
            float4 bv = *(const float4*)&s_B[buf * 512 + tt * NST + nq * 4];
            float4 cv = *(const float4*)&s_C[buf * 512 + tt * NST + nq * 4];
            float dx = del * xv;
            float e0 = ex2f(del * A0), e1 = ex2f(del * A1);
            float e2 = ex2f(del * A2), e3 = ex2f(del * A3);
            h0 = fmaf(e0, h0, dx * bv.x);
            h1 = fmaf(e1, h1, dx * bv.y);
            h2 = fmaf(e2, h2, dx * bv.z);
            h3 = fmaf(e3, h3, dx * bv.w);
            float yv = h0 * cv.x;
            yv = fmaf(h1, cv.y, yv);
            yv = fmaf(h2, cv.z, yv);
            yv = fmaf(h3, cv.w, yv);
            yv += __shfl_xor_sync(0xffffffffu, yv, 1);
            yv += __shfl_xor_sync(0xffffffffu, yv, 2);
            if (nq == 0) {
                float r  = s_res[buf * 2048 + tt * SD + dl];
                float y  = fmaf(xv, Dd, yv);
                float zv = y * (r / (1.f + __expf(-r)));
                g_ah[(size_t)(t0 + tt) * DI + d] = __float2half_rn(zv);
            }
        }
        __syncthreads();
        buf ^= 1;
    }
}

// ============================================================================
// launch
// ============================================================================
extern "C" void kernel_launch(void* const* d_in, const int* in_sizes, int n_in,
                              void* d_out, int out_size)
{
    const float* x      = (const float*)d_in[0];
    const float* W_in   = (const float*)d_in[1];
    const float* b_in   = (const float*)d_in[2];
    const float* W_conv = (const float*)d_in[3];
    const float* b_conv = (const float*)d_in[4];
    const float* W_x    = (const float*)d_in[5];
    const float* b_x    = (const float*)d_in[6];
    const float* W_out  = (const float*)d_in[7];
    const float* b_out  = (const float*)d_in[8];
    const float* A_log  = (const float*)d_in[9];
    const float* Dv     = (const float*)d_in[10];
    float* out = (float*)d_out;

    float *xr, *proj;
    __half *ah, *win_h, *wx_h, *wout_h;
    cudaGetSymbolAddress((void**)&xr,     g_xr);
    cudaGetSymbolAddress((void**)&proj,   g_proj);
    cudaGetSymbolAddress((void**)&ah,     g_ah);
    cudaGetSymbolAddress((void**)&win_h,  g_win_h);
    cudaGetSymbolAddress((void**)&wx_h,   g_wx_h);
    cudaGetSymbolAddress((void**)&wout_h, g_wout_h);

    static bool attr_done = false;
    if (!attr_done) {
        cudaFuncSetAttribute(gemm_mma<0>, cudaFuncAttributeMaxDynamicSharedMemorySize, GEMM_SMEM);
        cudaFuncSetAttribute(gemm_mma<1>, cudaFuncAttributeMaxDynamicSharedMemorySize, GEMM_SMEM);
        cudaFuncSetAttribute(scan_p3,     cudaFuncAttributeMaxDynamicSharedMemorySize, P3_SMEM);
        attr_done = true;
    }

    cvt_all<<<(N4_TOT + 255) / 256, 256>>>(x, W_in, W_x, W_out);

    {   // GEMM1: xr = x @ W_in.T + b_in
        dim3 grid((2 * DI) / 128, L_SEQ / 128);
        gemm_mma<0><<<grid, 256, GEMM_SMEM>>>(ah, win_h, b_in, xr,
                                              2 * DI, DM, 2 * DI);
    }
    conv_silu_k<<<(L_SEQ * DI / 4) / 256, 256>>>(W_conv, b_conv);

    {   // GEMM2: proj = xi @ W_x.T + b_x (softplus on delta)
        dim3 grid((NPROJ + 127) / 128, L_SEQ / 128);
        gemm_mma<1><<<grid, 256, GEMM_SMEM>>>(ah, wx_h, b_x, proj,
                                              NPROJ, DI, NPROJ);
    }
    {   // chunked scan
        dim3 g1(DI / SD, NCH);
        scan_p1<<<g1, 256>>>(A_log);
        scan_comb<<<(DI * NST / 4) / 256, 256>>>();
        scan_p3<<<g1, 256, P3_SMEM>>>(A_log, Dv);
    }
    {   // GEMM3: out = z @ W_out.T + b_out
        dim3 grid(DM / 128, L_SEQ / 128);
        gemm_mma<0><<<grid, 256, GEMM_SMEM>>>(ah, wout_h, b_out, out,
                                              DM, DI, DM);
    }
}

// round 12
// speedup vs baseline: 1.7315x; 1.1346x over previous
#include <cuda_runtime.h>
#include <cuda_fp16.h>
#include <math.h>
#include <stdint.h>

// ---------------- problem constants ----------------
#define L_SEQ 2048
#define DM    1024
#define DI    2048
#define NST   16
#define KC    4
#define NPROJ (DI + 2*NST)   // 2080

#define NCH   32             // scan chunks (was 16)
#define CH    64             // steps per chunk
#define TT1   32             // p1 time tile
#define TT3   16             // p3 time tile
#define SD    64

// ---------------- scratch (device globals) ----------------
__device__ float g_xr  [L_SEQ * 2 * DI];
__device__ float g_xi  [L_SEQ * DI];
__device__ float g_proj[L_SEQ * NPROJ];

__device__ __half g_ah    [L_SEQ * DI];
__device__ __half g_win_h [2 * DI * DM];
__device__ __half g_wx_h  [NPROJ * DI];
__device__ __half g_wout_h[DM * DI];

__device__ float g_cA[NCH * DI * NST];
__device__ float g_cB[NCH * DI * NST];
__device__ float g_h0[NCH * DI * NST];

__device__ __forceinline__ float softplus_f(float x) {
    return fmaxf(x, 0.f) + log1pf(expf(-fabsf(x)));
}

#define LOG2E 1.4426950408889634f

// ---------------- PTX helpers ----------------
__device__ __forceinline__ uint32_t smem_u32(const void* p) {
    uint32_t a;
    asm("{ .reg .u64 t; cvta.to.shared.u64 t, %1; cvt.u32.u64 %0, t; }" : "=r"(a) : "l"(p));
    return a;
}
__device__ __forceinline__ void cp_async16(uint32_t sm, const void* gm) {
    asm volatile("cp.async.ca.shared.global [%0], [%1], 16;" :: "r"(sm), "l"(gm));
}
__device__ __forceinline__ void cp_async16p(void* sm, const void* gm) {
    cp_async16(smem_u32(sm), gm);
}
__device__ __forceinline__ void cp_commit() { asm volatile("cp.async.commit_group;"); }
template<int N> __device__ __forceinline__ void cp_wait() {
    asm volatile("cp.async.wait_group %0;" :: "n"(N));
}
__device__ __forceinline__ void ldm_x4(uint32_t* r, uint32_t addr) {
    asm volatile("ldmatrix.sync.aligned.m8n8.x4.shared.b16 {%0,%1,%2,%3}, [%4];"
        : "=r"(r[0]), "=r"(r[1]), "=r"(r[2]), "=r"(r[3]) : "r"(addr));
}
__device__ __forceinline__ void mma_f16(float* d, const uint32_t* a, const uint32_t* b) {
    asm volatile(
        "mma.sync.aligned.m16n8k16.row.col.f32.f16.f16.f32 "
        "{%0,%1,%2,%3}, {%4,%5,%6,%7}, {%8,%9}, {%0,%1,%2,%3};"
        : "+f"(d[0]), "+f"(d[1]), "+f"(d[2]), "+f"(d[3])
        : "r"(a[0]), "r"(a[1]), "r"(a[2]), "r"(a[3]), "r"(b[0]), "r"(b[1]));
}
__device__ __forceinline__ float ex2f(float x) {
    float r;
    asm("ex2.approx.f32 %0, %1;" : "=f"(r) : "f"(x));
    return r;
}

// ============================================================================
// One fused convert kernel: weights -> fp16; x -> fp16.
// ============================================================================
#define N4_X   (L_SEQ * DM / 4)
#define N4_WIN (2 * DI * DM / 4)
#define N4_WX  (NPROJ * DI / 4)
#define N4_WO  (DM * DI / 4)
#define N4_TOT (N4_X + N4_WIN + N4_WX + N4_WO)

__global__ __launch_bounds__(256)
void cvt_all(const float* __restrict__ x, const float* __restrict__ W_in,
             const float* __restrict__ W_x, const float* __restrict__ W_out)
{
    int i = blockIdx.x * blockDim.x + threadIdx.x;
    if (i >= N4_TOT) return;

    const float* src; __half* dst; int j;
    if (i < N4_X)                       { j = i;                         src = x;     dst = g_ah; }
    else if (i < N4_X + N4_WIN)         { j = i - N4_X;                  src = W_in;  dst = g_win_h; }
    else if (i < N4_X + N4_WIN + N4_WX) { j = i - N4_X - N4_WIN;         src = W_x;   dst = g_wx_h; }
    else                                { j = i - N4_X - N4_WIN - N4_WX; src = W_out; dst = g_wout_h; }
    float4 v = ((const float4*)src)[j];
    ((__half2*)dst)[j*2+0] = __half2(__float2half_rn(v.x), __float2half_rn(v.y));
    ((__half2*)dst)[j*2+1] = __half2(__float2half_rn(v.z), __float2half_rn(v.w));
}

// ============================================================================
// fp16 GEMM via mma.sync m16n8k16 (single-term A) — at the mma.sync ceiling.
// ============================================================================
#define ROWB  144
#define MATB  (128 * ROWB)
#define GEMM_SMEM (2 * 2 * MATB)   // 73728

__device__ __forceinline__ void gemm_load_stage(
    uint32_t sb, int buf, int k0,
    const __half* __restrict__ Ah, const __half* __restrict__ Wh,
    int m0, int n0, int Nc, int Kd, int tid)
{
    uint32_t base = sb + buf * (2 * MATB);
#pragma unroll
    for (int it = 0; it < 8; it++) {
        int q   = tid + it * 256;
        int mat = q >> 10;
        int rem = q & 1023;
        int row = rem >> 3;
        int ch  = rem & 7;
        uint32_t dst = base + mat * MATB + row * ROWB + ch * 16;
        const __half* src;
        if (mat == 0) {
            src = Ah + (size_t)(m0 + row) * Kd + k0 + ch * 8;
        } else {
            int wr = n0 + row; if (wr >= Nc) wr = Nc - 1;
            src = Wh + (size_t)wr * Kd + k0 + ch * 8;
        }
        cp_async16(dst, src);
    }
    cp_commit();
}

template<int ACT>
__global__ __launch_bounds__(256, 2)
void gemm_mma(const __half* __restrict__ Ah, const __half* __restrict__ Wh,
              const float* __restrict__ bias, float* __restrict__ C,
              int Nc, int Kd, int ldc)
{
    extern __shared__ char smraw[];
    uint32_t sb = smem_u32(smraw);

    int tid  = threadIdx.x;
    int wid  = tid >> 5;
    int lane = tid & 31;
    int wm   = wid & 3;
    int wn   = wid >> 2;
    int m0 = blockIdx.y * 128;
    int n0 = blockIdx.x * 128;

    float acc[2][8][4];
#pragma unroll
    for (int i = 0; i < 2; i++)
#pragma unroll
        for (int j = 0; j < 8; j++)
#pragma unroll
            for (int k = 0; k < 4; k++) acc[i][j][k] = 0.f;

    int aRow = wm * 32 + (lane & 15);
    int aColHalf = (lane >> 4) << 3;
    int bRow = wn * 64 + ((lane >> 4) & 1) * 8 + (lane & 7);
    int bColHalf = ((lane >> 3) & 1) << 3;

    const int NSTAGE = Kd / 64;
    gemm_load_stage(sb, 0, 0, Ah, Wh, m0, n0, Nc, Kd, tid);

    int buf = 0;
    for (int s = 0; s < NSTAGE; s++) {
        cp_wait<0>();
        __syncthreads();
        if (s + 1 < NSTAGE)
            gemm_load_stage(sb, buf ^ 1, (s + 1) * 64, Ah, Wh, m0, n0, Nc, Kd, tid);

        uint32_t bA = sb + buf * (2 * MATB);
        uint32_t bW = bA + MATB;
#pragma unroll
        for (int kc = 0; kc < 4; kc++) {
            int acol2 = (kc * 16 + aColHalf) * 2;
            int bcol2 = (kc * 16 + bColHalf) * 2;
            uint32_t ah[2][4], bh[4][4];
#pragma unroll
            for (int mt = 0; mt < 2; mt++) {
                uint32_t off = (uint32_t)((aRow + mt * 16) * ROWB + acol2);
                ldm_x4(ah[mt], bA + off);
            }
#pragma unroll
            for (int ntp = 0; ntp < 4; ntp++) {
                uint32_t off = (uint32_t)((bRow + ntp * 16) * ROWB + bcol2);
                ldm_x4(bh[ntp], bW + off);
            }
#pragma unroll
            for (int ntp = 0; ntp < 4; ntp++) {
#pragma unroll
                for (int mt = 0; mt < 2; mt++) {
                    mma_f16(acc[mt][2*ntp+0], ah[mt], bh[ntp] + 0);
                    mma_f16(acc[mt][2*ntp+1], ah[mt], bh[ntp] + 2);
                }
            }
        }
        buf ^= 1;
    }

#pragma unroll
    for (int mt = 0; mt < 2; mt++) {
        int r0 = m0 + wm * 32 + mt * 16 + (lane >> 2);
#pragma unroll
        for (int nt = 0; nt < 8; nt++) {
            int c = n0 + wn * 64 + nt * 8 + 2 * (lane & 3);
            if (c < Nc) {
                float b0 = bias[c], b1 = bias[c + 1];
                float v0 = acc[mt][nt][0] + b0;
                float v1 = acc[mt][nt][1] + b1;
                float v2 = acc[mt][nt][2] + b0;
                float v3 = acc[mt][nt][3] + b1;
                if (ACT == 1) {
                    if (c     < DI) { v0 = softplus_f(v0); v2 = softplus_f(v2); }
                    if (c + 1 < DI) { v1 = softplus_f(v1); v3 = softplus_f(v3); }
                }
                *(float2*)&C[(size_t)r0 * ldc + c]       = make_float2(v0, v1);
                *(float2*)&C[(size_t)(r0 + 8) * ldc + c] = make_float2(v2, v3);
            }
        }
    }
}

// ============================================================================
// Depthwise causal conv (K=4) + silu.
// Each thread: 4 channels x 8 timesteps, rolling window (weights amortized).
// ============================================================================
__global__ __launch_bounds__(256)
void conv_silu_k(const float* __restrict__ Wc, const float* __restrict__ bc)
{
    int idx = blockIdx.x * blockDim.x + threadIdx.x;   // over (L/8) * (DI/4)
    int tblk = idx >> 9;              // 0..255  (8-step block)
    int d4   = (idx & 511) << 2;      // channel quad
    int t0 = tblk * 8;

    float4 w0 = *(const float4*)&Wc[(d4 + 0) * KC];
    float4 w1 = *(const float4*)&Wc[(d4 + 1) * KC];
    float4 w2 = *(const float4*)&Wc[(d4 + 2) * KC];
    float4 w3 = *(const float4*)&Wc[(d4 + 3) * KC];
    float4 b  = *(const float4*)&bc[d4];

    const float4 z4 = make_float4(0.f, 0.f, 0.f, 0.f);
    float4 vm3 = (t0 >= 3) ? *(const float4*)&g_xr[(size_t)(t0-3) * (2*DI) + d4] : z4;
    float4 vm2 = (t0 >= 2) ? *(const float4*)&g_xr[(size_t)(t0-2) * (2*DI) + d4] : z4;
    float4 vm1 = (t0 >= 1) ? *(const float4*)&g_xr[(size_t)(t0-1) * (2*DI) + d4] : z4;

#pragma unroll
    for (int s = 0; s < 8; s++) {
        int t = t0 + s;
        float4 v0 = *(const float4*)&g_xr[(size_t)t * (2*DI) + d4];
        float ax = fmaf(w0.w, v0.x, fmaf(w0.z, vm1.x, fmaf(w0.y, vm2.x, fmaf(w0.x, vm3.x, b.x))));
        float ay = fmaf(w1.w, v0.y, fmaf(w1.z, vm1.y, fmaf(w1.y, vm2.y, fmaf(w1.x, vm3.y, b.y))));
        float az = fmaf(w2.w, v0.z, fmaf(w2.z, vm1.z, fmaf(w2.y, vm2.z, fmaf(w2.x, vm3.z, b.z))));
        float aw = fmaf(w3.w, v0.w, fmaf(w3.z, vm1.w, fmaf(w3.y, vm2.w, fmaf(w3.x, vm3.w, b.w))));
        float s0 = ax / (1.f + __expf(-ax));
        float s1 = ay / (1.f + __expf(-ay));
        float s2 = az / (1.f + __expf(-az));
        float s3 = aw / (1.f + __expf(-aw));
        size_t o = (size_t)t * DI + d4;
        *(float4*)&g_xi[o] = make_float4(s0, s1, s2, s3);
        *(__half2*)&g_ah[o]     = __half2(__float2half_rn(s0), __float2half_rn(s1));
        *(__half2*)&g_ah[o + 2] = __half2(__float2half_rn(s2), __float2half_rn(s3));
        vm3 = vm2; vm2 = vm1; vm1 = v0;
    }
}

// ============================================================================
// Chunked selective scan, NCH=32 chunks of CH=64.
// p1 uses the S-trick: prod exp2(A'·del) = exp2(A'·Σdel).
// ============================================================================
__global__ __launch_bounds__(256, 1)
void scan_p1(const float* __restrict__ A_log)
{
    __shared__ float s_delta[2][TT1][SD];   // 16 KB
    __shared__ float s_xi   [2][TT1][SD];   // 16 KB
    __shared__ float s_B    [2][TT1][NST];  //  4 KB

    int tid = threadIdx.x;
    int nq = tid & 3;
    int dl = tid >> 2;
    int dbase = blockIdx.x * SD;
    int d = dbase + dl;
    int chunk = blockIdx.y;
    int tbase = chunk * CH;

    float4 alv = *(const float4*)&A_log[d * NST + nq * 4];
    float A0 = -__expf(alv.x) * LOG2E, A1 = -__expf(alv.y) * LOG2E;
    float A2 = -__expf(alv.z) * LOG2E, A3 = -__expf(alv.w) * LOG2E;

    float S = 0.f;
    float h0 = 0.f, h1 = 0.f, h2 = 0.f, h3 = 0.f;

    auto issue = [&](int t0, int buf) {
        for (int q = tid; q < 1152; q += 256) {
            if (q < 1024) {
                int arr = q >> 9;
                int rem = q & 511;
                int tq  = rem >> 4;
                int v   = (rem & 15) * 4;
                int t   = tbase + t0 + tq;
                if (arr == 0)
                    cp_async16p(&s_delta[buf][tq][v], g_proj + (size_t)t * NPROJ + dbase + v);
                else
                    cp_async16p(&s_xi[buf][tq][v], g_xi + (size_t)t * DI + dbase + v);
            } else {
                int rem = q - 1024;
                int tq  = rem >> 2;
                int v   = (rem & 3) * 4;
                int t   = tbase + t0 + tq;
                cp_async16p(&s_B[buf][tq][v], g_proj + (size_t)t * NPROJ + DI + v);
            }
        }
        cp_commit();
    };

    issue(0, 0);
    int buf = 0;
    const int NT2 = CH / TT1;   // 2
    for (int it = 0; it < NT2; it++) {
        if (it + 1 < NT2) { issue((it + 1) * TT1, buf ^ 1); cp_wait<1>(); }
        else              { cp_wait<0>(); }
        __syncthreads();
#pragma unroll
        for (int tt = 0; tt < TT1; tt++) {
            float del = s_delta[buf][tt][dl];
            float xv  = s_xi[buf][tt][dl];
            float4 bv = *(const float4*)&s_B[buf][tt][nq * 4];
            float dx = del * xv;
            float e0 = ex2f(del * A0), e1 = ex2f(del * A1);
            float e2 = ex2f(del * A2), e3 = ex2f(del * A3);
            S += del;
            h0 = fmaf(e0, h0, dx * bv.x);
            h1 = fmaf(e1, h1, dx * bv.y);
            h2 = fmaf(e2, h2, dx * bv.z);
            h3 = fmaf(e3, h3, dx * bv.w);
        }
        __syncthreads();
        buf ^= 1;
    }
    int idx = (chunk * DI + d) * NST + nq * 4;
    *(float4*)&g_cA[idx] = make_float4(ex2f(A0 * S), ex2f(A1 * S),
                                       ex2f(A2 * S), ex2f(A3 * S));
    *(float4*)&g_cB[idx] = make_float4(h0, h1, h2, h3);
}

__global__ __launch_bounds__(256)
void scan_comb()
{
    int dn4 = (blockIdx.x * blockDim.x + threadIdx.x) * 4;
    float4 h = make_float4(0.f, 0.f, 0.f, 0.f);
#pragma unroll
    for (int c = 0; c < NCH; c++) {
        int idx = c * (DI * NST) + dn4;
        *(float4*)&g_h0[idx] = h;
        float4 a = *(const float4*)&g_cA[idx];
        float4 b = *(const float4*)&g_cB[idx];
        h.x = fmaf(a.x, h.x, b.x);
        h.y = fmaf(a.y, h.y, b.y);
        h.z = fmaf(a.z, h.z, b.z);
        h.w = fmaf(a.w, h.w, b.w);
    }
}

// p3: TT=16, dynamic smem 28 KB -> high co-residency for the 1024-block grid
#define P3_SMEM (7168 * 4)   // floats: 3*2048 + 2*512

__global__ __launch_bounds__(256, 1)
void scan_p3(const float* __restrict__ A_log, const float* __restrict__ Dv)
{
    extern __shared__ float sm[];
    float* s_delta = sm;            // [2][TT3][SD] = 2048 floats
    float* s_xi    = sm + 2048;
    float* s_res   = sm + 4096;
    float* s_B     = sm + 6144;     // [2][TT3][NST] = 512 floats
    float* s_C     = sm + 6656;

    int tid = threadIdx.x;
    int nq = tid & 3;
    int dl = tid >> 2;
    int dbase = blockIdx.x * SD;
    int d = dbase + dl;
    int chunk = blockIdx.y;
    int tbase = chunk * CH;

    float4 alv = *(const float4*)&A_log[d * NST + nq * 4];
    float A0 = -__expf(alv.x) * LOG2E, A1 = -__expf(alv.y) * LOG2E;
    float A2 = -__expf(alv.z) * LOG2E, A3 = -__expf(alv.w) * LOG2E;
    float Dd = Dv[d];

    float4 hv = *(const float4*)&g_h0[(chunk * DI + d) * NST + nq * 4];
    float h0 = hv.x, h1 = hv.y, h2 = hv.z, h3 = hv.w;

    auto issue = [&](int t0, int buf) {
        for (int q = tid; q < 896; q += 256) {
            if (q < 768) {
                int arr = q >> 8;
                int rem = q & 255;
                int tq  = rem >> 4;
                int v   = (rem & 15) * 4;
                int t   = tbase + t0 + tq;
                int so  = buf * 1024 + tq * SD + v;
                if      (arr == 0) cp_async16p(&s_delta[so], g_proj + (size_t)t * NPROJ + dbase + v);
                else if (arr == 1) cp_async16p(&s_xi[so],    g_xi   + (size_t)t * DI + dbase + v);
                else               cp_async16p(&s_res[so],   g_xr   + (size_t)t * (2*DI) + DI + dbase + v);
            } else {
                int rem = q - 768;
                int arr = rem >> 6;
                int r2  = rem & 63;
                int tq  = r2 >> 2;
                int v   = (r2 & 3) * 4;
                int t   = tbase + t0 + tq;
                int so  = buf * 256 + tq * NST + v;
                if (arr == 0) cp_async16p(&s_B[so], g_proj + (size_t)t * NPROJ + DI + v);
                else          cp_async16p(&s_C[so], g_proj + (size_t)t * NPROJ + DI + NST + v);
            }
        }
        cp_commit();
    };

    issue(0, 0);
    int buf = 0;
    const int NT2 = CH / TT3;   // 4
    for (int it = 0; it < NT2; it++) {
        if (it + 1 < NT2) { issue((it + 1) * TT3, buf ^ 1); cp_wait<1>(); }
        else              { cp_wait<0>(); }
        __syncthreads();

        int t0 = tbase + it * TT3;
#pragma unroll
        for (int tt = 0; tt < TT3; tt++) {
            float del = s_delta[buf * 1024 + tt * SD + dl];
            float xv  = s_xi   [buf * 1024 + tt * SD + dl];
            float4 bv = *(const float4*)&s_B[buf * 256 + tt * NST + nq * 4];
            float4 cv = *(const float4*)&s_C[buf * 256 + tt * NST + nq * 4];
            float dx = del * xv;
            float e0 = ex2f(del * A0), e1 = ex2f(del * A1);
            float e2 = ex2f(del * A2), e3 = ex2f(del * A3);
            h0 = fmaf(e0, h0, dx * bv.x);
            h1 = fmaf(e1, h1, dx * bv.y);
            h2 = fmaf(e2, h2, dx * bv.z);
            h3 = fmaf(e3, h3, dx * bv.w);
            float yv = h0 * cv.x;
            yv = fmaf(h1, cv.y, yv);
            yv = fmaf(h2, cv.z, yv);
            yv = fmaf(h3, cv.w, yv);
            yv += __shfl_xor_sync(0xffffffffu, yv, 1);
            yv += __shfl_xor_sync(0xffffffffu, yv, 2);
            if (nq == 0) {
                float r  = s_res[buf * 1024 + tt * SD + dl];
                float y  = fmaf(xv, Dd, yv);
                float zv = y * (r / (1.f + __expf(-r)));
                g_ah[(size_t)(t0 + tt) * DI + d] = __float2half_rn(zv);
            }
        }
        __syncthreads();
        buf ^= 1;
    }
}

// ============================================================================
// launch
// ============================================================================
extern "C" void kernel_launch(void* const* d_in, const int* in_sizes, int n_in,
                              void* d_out, int out_size)
{
    const float* x      = (const float*)d_in[0];
    const float* W_in   = (const float*)d_in[1];
    const float* b_in   = (const float*)d_in[2];
    const float* W_conv = (const float*)d_in[3];
    const float* b_conv = (const float*)d_in[4];
    const float* W_x    = (const float*)d_in[5];
    const float* b_x    = (const float*)d_in[6];
    const float* W_out  = (const float*)d_in[7];
    const float* b_out  = (const float*)d_in[8];
    const float* A_log  = (const float*)d_in[9];
    const float* Dv     = (const float*)d_in[10];
    float* out = (float*)d_out;

    float *xr, *proj;
    __half *ah, *win_h, *wx_h, *wout_h;
    cudaGetSymbolAddress((void**)&xr,     g_xr);
    cudaGetSymbolAddress((void**)&proj,   g_proj);
    cudaGetSymbolAddress((void**)&ah,     g_ah);
    cudaGetSymbolAddress((void**)&win_h,  g_win_h);
    cudaGetSymbolAddress((void**)&wx_h,   g_wx_h);
    cudaGetSymbolAddress((void**)&wout_h, g_wout_h);

    static bool attr_done = false;
    if (!attr_done) {
        cudaFuncSetAttribute(gemm_mma<0>, cudaFuncAttributeMaxDynamicSharedMemorySize, GEMM_SMEM);
        cudaFuncSetAttribute(gemm_mma<1>, cudaFuncAttributeMaxDynamicSharedMemorySize, GEMM_SMEM);
        cudaFuncSetAttribute(scan_p3,     cudaFuncAttributeMaxDynamicSharedMemorySize, P3_SMEM);
        attr_done = true;
    }

    cvt_all<<<(N4_TOT + 255) / 256, 256>>>(x, W_in, W_x, W_out);

    {   // GEMM1: xr = x @ W_in.T + b_in
        dim3 grid((2 * DI) / 128, L_SEQ / 128);
        gemm_mma<0><<<grid, 256, GEMM_SMEM>>>(ah, win_h, b_in, xr,
                                              2 * DI, DM, 2 * DI);
    }
    conv_silu_k<<<((L_SEQ / 8) * (DI / 4)) / 256, 256>>>(W_conv, b_conv);

    {   // GEMM2: proj = xi @ W_x.T + b_x (softplus on delta)
        dim3 grid((NPROJ + 127) / 128, L_SEQ / 128);
        gemm_mma<1><<<grid, 256, GEMM_SMEM>>>(ah, wx_h, b_x, proj,
                                              NPROJ, DI, NPROJ);
    }
    {   // chunked scan (32 chunks of 64)
        dim3 g1(DI / SD, NCH);
        scan_p1<<<g1, 256>>>(A_log);
        scan_comb<<<(DI * NST / 4) / 256, 256>>>();
        scan_p3<<<g1, 256, P3_SMEM>>>(A_log, Dv);
    }
    {   // GEMM3: out = z @ W_out.T + b_out
        dim3 grid(DM / 128, L_SEQ / 128);
        gemm_mma<0><<<grid, 256, GEMM_SMEM>>>(ah, wout_h, b_out, out,
                                              DM, DI, DM);
    }
}